// round 11
// baseline (speedup 1.0000x reference)
#include <cuda_runtime.h>
#include <cuda_bf16.h>
#include <math.h>
#include <stdint.h>

// Problem constants
#define B_   2
#define H_   16
#define T_   2048
#define D_   1024
#define HD_  64
#define M_   (B_*T_)      // 4096 rows
#define NQKV_ (3*D_)      // 3072
#define K_   1024

// Scratch (device globals: allocation-free rule)
__device__ float g_q[B_*H_*T_*HD_];   // fp32 pre-rope
__device__ float g_k[B_*H_*T_*HD_];
__device__ float g_v[B_*H_*T_*HD_];

// bf16 split operands
__device__ __align__(16) __nv_bfloat16 g_xh[M_*D_],    g_xl[M_*D_];
__device__ __align__(16) __nv_bfloat16 g_wqkvTh[NQKV_*D_], g_wqkvTl[NQKV_*D_];
__device__ __align__(16) __nv_bfloat16 g_woutTh[D_*D_],   g_woutTl[D_*D_];
__device__ __align__(16) __nv_bfloat16 g_atth[M_*D_],  g_attl[M_*D_];
__device__ __align__(16) __nv_bfloat16 g_qh[B_*H_*T_*HD_], g_ql[B_*H_*T_*HD_];  // [bh][t][d]
__device__ __align__(16) __nv_bfloat16 g_kh[B_*H_*T_*HD_], g_kl[B_*H_*T_*HD_];  // [bh][t][d]
__device__ __align__(16) __nv_bfloat16 g_vth[B_*H_*T_*HD_], g_vtl[B_*H_*T_*HD_]; // [bh][d][t]

__device__ __forceinline__ uint32_t smem_u32(const void* p) {
    uint32_t a;
    asm("{ .reg .u64 t; cvta.to.shared.u64 t, %1; cvt.u32.u64 %0, t; }" : "=r"(a) : "l"(p));
    return a;
}
__device__ __forceinline__ void cp_async16(uint32_t dst, const void* src) {
    asm volatile("cp.async.cg.shared.global [%0], [%1], 16;" :: "r"(dst), "l"(src));
}
__device__ __forceinline__ void cp_commit() { asm volatile("cp.async.commit_group;" ::: "memory"); }
__device__ __forceinline__ void cp_wait0()  { asm volatile("cp.async.wait_group 0;" ::: "memory"); }
__device__ __forceinline__ void cp_wait1()  { asm volatile("cp.async.wait_group 1;" ::: "memory"); }
__device__ __forceinline__ void ldsm4(uint32_t r[4], uint32_t addr) {
    asm volatile("ldmatrix.sync.aligned.m8n8.x4.shared.b16 {%0,%1,%2,%3}, [%4];"
        : "=r"(r[0]), "=r"(r[1]), "=r"(r[2]), "=r"(r[3]) : "r"(addr));
}
__device__ __forceinline__ void mma_bf16(float c[4], const uint32_t a[4], const uint32_t b[2]) {
    asm volatile(
        "mma.sync.aligned.m16n8k16.row.col.f32.bf16.bf16.f32 "
        "{%0,%1,%2,%3}, {%4,%5,%6,%7}, {%8,%9}, {%0,%1,%2,%3};"
        : "+f"(c[0]), "+f"(c[1]), "+f"(c[2]), "+f"(c[3])
        : "r"(a[0]), "r"(a[1]), "r"(a[2]), "r"(a[3]), "r"(b[0]), "r"(b[1]));
}
__device__ __forceinline__ void split1(float v, __nv_bfloat16& h, __nv_bfloat16& l) {
    h = __float2bfloat16(v);
    l = __float2bfloat16(v - __bfloat162float(h));
}
__device__ __forceinline__ void split2(float x, float y, uint32_t& h, uint32_t& l) {
    __nv_bfloat16 hx, lx, hy, ly;
    split1(x, hx, lx); split1(y, hy, ly);
    __nv_bfloat162 hv(hx, hy), lv(lx, ly);
    h = *(uint32_t*)&hv; l = *(uint32_t*)&lv;
}

// ---------------------------------------------------------------------------
// Feeders (unchanged)
// ---------------------------------------------------------------------------
__global__ void split4_kernel(const float4* __restrict__ src,
                              __nv_bfloat162* __restrict__ h,
                              __nv_bfloat162* __restrict__ l, int n4)
{
    const int i = blockIdx.x * blockDim.x + threadIdx.x;
    if (i >= n4) return;
    const float4 v = src[i];
    __nv_bfloat16 hx, lx, hy, ly, hz, lz, hw, lw;
    split1(v.x, hx, lx); split1(v.y, hy, ly);
    split1(v.z, hz, lz); split1(v.w, hw, lw);
    h[2*i]   = __nv_bfloat162(hx, hy);
    h[2*i+1] = __nv_bfloat162(hz, hw);
    l[2*i]   = __nv_bfloat162(lx, ly);
    l[2*i+1] = __nv_bfloat162(lz, lw);
}

__global__ void splitT_kernel(const float* __restrict__ src,
                              __nv_bfloat16* __restrict__ hT,
                              __nv_bfloat16* __restrict__ lT, int R, int C)
{
    __shared__ float tile[32][33];
    const int bx = blockIdx.x * 32, by = blockIdx.y * 32;
    const int tx = threadIdx.x, ty = threadIdx.y;
#pragma unroll
    for (int i = 0; i < 32; i += 8)
        tile[ty + i][tx] = src[(size_t)(by + ty + i) * C + bx + tx];
    __syncthreads();
#pragma unroll
    for (int i = 0; i < 32; i += 8) {
        const float v = tile[tx][ty + i];
        __nv_bfloat16 h, l;
        split1(v, h, l);
        const size_t o = (size_t)(bx + ty + i) * R + by + tx;
        hT[o] = h; lT[o] = l;
    }
}

__global__ void vsplitT_kernel()
{
    __shared__ float tile[32][33];
    const int bt = blockIdx.x * 32, bd = blockIdx.y * 32, bh = blockIdx.z;
    const int tx = threadIdx.x, ty = threadIdx.y;
    const float* src = g_v + (size_t)bh * T_ * HD_;
    __nv_bfloat16* dh = g_vth + (size_t)bh * HD_ * T_;
    __nv_bfloat16* dl = g_vtl + (size_t)bh * HD_ * T_;
#pragma unroll
    for (int i = 0; i < 32; i += 8)
        tile[ty + i][tx] = src[(size_t)(bt + ty + i) * HD_ + bd + tx];
    __syncthreads();
#pragma unroll
    for (int i = 0; i < 32; i += 8) {
        const float v = tile[tx][ty + i];
        __nv_bfloat16 h, l;
        split1(v, h, l);
        const size_t o = (size_t)(bd + ty + i) * T_ + bt + tx;
        dh[o] = h; dl[o] = l;
    }
}

// ---------------------------------------------------------------------------
// bf16 split-GEMM with ldmatrix fragment loading (unchanged from R10).
// ---------------------------------------------------------------------------
#define PB    40
#define MATB  (128 * PB * 2)
#define BUFB  (4 * MATB)
#define BGEMM_SMEM (2 * BUFB)

template<int MODE>
__global__ __launch_bounds__(256, 2)
void bgemm(const __nv_bfloat16* __restrict__ Ah, const __nv_bfloat16* __restrict__ Al,
           const __nv_bfloat16* __restrict__ Bh, const __nv_bfloat16* __restrict__ Bl,
           float* __restrict__ Cout, int N, int K)
{
    extern __shared__ char smc[];
    const uint32_t sb = smem_u32(smc);

    const int tid  = threadIdx.x;
    const int wid  = tid >> 5;
    const int lane = tid & 31;
    const int g    = lane >> 2;
    const int tig  = lane & 3;
    const int lq   = lane >> 3;
    const int lr   = lane & 7;
    const int warp_m = wid >> 2;
    const int warp_n = wid & 3;
    const int bm = blockIdx.y;
    const int bn = blockIdx.x;

    const char* gsrc[4] = {
        (const char*)(Ah + (size_t)bm * 128 * K),
        (const char*)(Al + (size_t)bm * 128 * K),
        (const char*)(Bh + (size_t)bn * 128 * K),
        (const char*)(Bl + (size_t)bn * 128 * K)
    };
    const size_t grs = (size_t)K * 2;

    float acc[4][4][4];
#pragma unroll
    for (int i = 0; i < 4; i++)
#pragma unroll
        for (int j = 0; j < 4; j++)
#pragma unroll
            for (int e = 0; e < 4; e++) acc[i][j][e] = 0.0f;

    const int NT = K / 32;

#pragma unroll
    for (int p = 0; p < 8; p++) {
        const int c   = tid + p * 256;
        const int mat = c >> 9;
        const int r   = (c >> 2) & 127;
        const int q   = (c & 3) * 16;
        cp_async16(sb + mat * MATB + r * (PB * 2) + q,
                   gsrc[mat] + (size_t)r * grs + q);
    }
    cp_commit();
    cp_wait0();
    __syncthreads();

    const uint32_t aRow = lr + (lq & 1) * 8;
    const uint32_t aCol = (lq >> 1) * 16;
    const uint32_t bRow = lr + (lq >> 1) * 8;
    const uint32_t bCol = (lq & 1) * 16;

    for (int t = 0; t < NT; t++) {
        const int buf = t & 1;

        if (t + 1 < NT) {
            const uint32_t db = sb + (buf ^ 1) * BUFB;
            const size_t kb = (size_t)(t + 1) * 64;
#pragma unroll
            for (int p = 0; p < 8; p++) {
                const int c   = tid + p * 256;
                const int mat = c >> 9;
                const int r   = (c >> 2) & 127;
                const int q   = (c & 3) * 16;
                cp_async16(db + mat * MATB + r * (PB * 2) + q,
                           gsrc[mat] + (size_t)r * grs + kb + q);
            }
            cp_commit();
        }

        const uint32_t base = sb + buf * BUFB;
#pragma unroll
        for (int ks = 0; ks < 2; ks++) {
            const uint32_t ko = ks * 32;

            uint32_t ah[4][4], al[4][4], bh[4][2], bl[4][2];
#pragma unroll
            for (int i = 0; i < 4; i++) {
                const uint32_t ao = (warp_m * 64 + i * 16 + aRow) * (PB * 2) + ko + aCol;
                ldsm4(ah[i], base + ao);
                ldsm4(al[i], base + MATB + ao);
            }
#pragma unroll
            for (int jp = 0; jp < 2; jp++) {
                const uint32_t bo = (warp_n * 32 + jp * 16 + bRow) * (PB * 2) + ko + bCol;
                uint32_t th[4], tl[4];
                ldsm4(th, base + 2 * MATB + bo);
                bh[2*jp][0] = th[0]; bh[2*jp][1] = th[1];
                bh[2*jp+1][0] = th[2]; bh[2*jp+1][1] = th[3];
                ldsm4(tl, base + 3 * MATB + bo);
                bl[2*jp][0] = tl[0]; bl[2*jp][1] = tl[1];
                bl[2*jp+1][0] = tl[2]; bl[2*jp+1][1] = tl[3];
            }

#pragma unroll
            for (int i = 0; i < 4; i++)
#pragma unroll
                for (int j = 0; j < 4; j++)
                    mma_bf16(acc[i][j], ah[i], bh[j]);
#pragma unroll
            for (int i = 0; i < 4; i++)
#pragma unroll
                for (int j = 0; j < 4; j++)
                    mma_bf16(acc[i][j], al[i], bh[j]);
#pragma unroll
            for (int i = 0; i < 4; i++)
#pragma unroll
                for (int j = 0; j < 4; j++)
                    mma_bf16(acc[i][j], ah[i], bl[j]);
        }

        if (t + 1 < NT) cp_wait0();
        __syncthreads();
    }

#pragma unroll
    for (int i = 0; i < 4; i++) {
        const int r0 = bm * 128 + warp_m * 64 + i * 16 + g;
#pragma unroll
        for (int j = 0; j < 4; j++) {
            const int c0 = bn * 128 + warp_n * 32 + j * 8 + tig * 2;
#pragma unroll
            for (int half = 0; half < 2; half++) {
                const int r = r0 + half * 8;
                const float2 v = make_float2(acc[i][j][half * 2], acc[i][j][half * 2 + 1]);
                if (MODE == 0) {
                    const int b    = r >> 11;
                    const int tt   = r & (T_ - 1);
                    const int part = c0 >> 10;
                    const int idx  = c0 & 1023;
                    const int h    = idx >> 6;
                    const int d    = idx & 63;
                    float* dst = (part == 0) ? g_q : (part == 1) ? g_k : g_v;
                    *(float2*)(dst + (((size_t)b * H_ + h) * T_ + tt) * HD_ + d) = v;
                } else {
                    *(float2*)(Cout + (size_t)r * N + c0) = v;
                }
            }
        }
    }
}

// ---------------------------------------------------------------------------
// RoPE (unchanged): fp32 q/k -> split bf16
// ---------------------------------------------------------------------------
__global__ void rope_kernel()
{
    const int idx = blockIdx.x * blockDim.x + threadIdx.x;
    const int j  = idx & 31;
    const int t  = (idx >> 5) & (T_ - 1);
    const int bh = idx >> 16;

    const float f = exp2f(-(float)j * (13.287712379549449f / 32.0f));
    float s, c;
    sincosf((float)t * f, &s, &c);

    const size_t base = ((size_t)bh * T_ + t) * HD_;
    float a0 = g_q[base + j], b0 = g_q[base + j + 32];
    float a1 = g_k[base + j], b1 = g_k[base + j + 32];
    const float q0 = a0 * c - b0 * s, q1 = b0 * c + a0 * s;
    const float k0 = a1 * c - b1 * s, k1 = b1 * c + a1 * s;
    __nv_bfloat16 h, l;
    split1(q0, h, l); g_qh[base + j] = h;      g_ql[base + j] = l;
    split1(q1, h, l); g_qh[base + j + 32] = h; g_ql[base + j + 32] = l;
    split1(k0, h, l); g_kh[base + j] = h;      g_kl[base + j] = l;
    split1(k1, h, l); g_kh[base + j + 32] = h; g_kl[base + j + 32] = l;
}

// ---------------------------------------------------------------------------
// Tensor-core flash attention: cp.async double-buffered K/V stages,
// ldmatrix fragments, causal diag-tile mma skips.
// ---------------------------------------------------------------------------
#define KPIT 72
#define VPIT 136
#define KBYTES (128 * KPIT * 2)          // 18432 B per K matrix
#define VBYTES (64 * VPIT * 2)           // 17408 B per V matrix
#define STAGEB (2 * KBYTES + 2 * VBYTES) // 71680 B per stage
#define FLASH_SMEM (2 * STAGEB)          // 143360 B

__global__ __launch_bounds__(256, 1)
void flash_tc()
{
    extern __shared__ __nv_bfloat16 smb[];
    const uint32_t sbase = smem_u32(smb);

    const int tid  = threadIdx.x;
    const int wid  = tid >> 5;
    const int lane = tid & 31;
    const int g    = lane >> 2;
    const int tig  = lane & 3;
    const int lq   = lane >> 3;
    const int lr   = lane & 7;
    const int qtile = (int)gridDim.x - 1 - (int)blockIdx.x;
    const int bh    = blockIdx.y;

    const size_t qkbase = ((size_t)bh * T_ + (size_t)qtile * 128) * HD_;
    const size_t kvrow0 = (size_t)bh * T_ * HD_;
    const size_t vtbase = (size_t)bh * HD_ * T_;

    const uint32_t aRow = lr + (lq & 1) * 8;
    const uint32_t aCol = (lq >> 1) * 16;
    const uint32_t bRow = lr + (lq >> 1) * 8;
    const uint32_t bCol = (lq & 1) * 16;

    // ---- stage Q (plain stores into stage0 K area), extract frags ----
    {
        const __nv_bfloat16* qsrc[2] = { g_qh + qkbase, g_ql + qkbase };
#pragma unroll
        for (int p = 0; p < 8; p++) {
            const int c   = tid + p * 256;
            const int mat = c >> 10;
            const int rem = c & 1023;
            const int r   = rem >> 3;
            const int c8  = (rem & 7) * 8;
            *(uint4*)(smb + mat * (128 * KPIT) + r * KPIT + c8) =
                *(const uint4*)(qsrc[mat] + r * HD_ + c8);
        }
    }
    __syncthreads();

    uint32_t qfh[4][4], qfl[4][4];
#pragma unroll
    for (int kb = 0; kb < 4; kb++) {
        const uint32_t qo = (16 * wid + aRow) * (KPIT * 2) + kb * 32 + aCol;
        ldsm4(qfh[kb], sbase + qo);
        ldsm4(qfl[kb], sbase + KBYTES + qo);
    }
    __syncthreads();   // all Q frags extracted before stage0 is overwritten

    // ---- async K/V tile stager ----
    auto stage_load = [&](int kv, int s) {
        const uint32_t stb = sbase + (uint32_t)s * STAGEB;
        const char* ksrc[2] = {
            (const char*)(g_kh + kvrow0 + (size_t)kv * 128 * HD_),
            (const char*)(g_kl + kvrow0 + (size_t)kv * 128 * HD_) };
        const char* vsrc[2] = {
            (const char*)(g_vth + vtbase + (size_t)kv * 128),
            (const char*)(g_vtl + vtbase + (size_t)kv * 128) };
#pragma unroll
        for (int p = 0; p < 8; p++) {
            const int c   = tid + p * 256;
            const int mat = c >> 10;
            const int rem = c & 1023;
            const int r   = rem >> 3;
            const int cb  = (rem & 7) * 16;
            cp_async16(stb + mat * KBYTES + r * (KPIT * 2) + cb,
                       ksrc[mat] + (size_t)r * (HD_ * 2) + cb);
        }
#pragma unroll
        for (int p = 0; p < 8; p++) {
            const int c   = tid + p * 256;
            const int mat = c >> 10;
            const int rem = c & 1023;
            const int d   = rem >> 4;
            const int cb  = (rem & 15) * 16;
            cp_async16(stb + 2 * KBYTES + mat * VBYTES + d * (VPIT * 2) + cb,
                       vsrc[mat] + (size_t)d * (T_ * 2) + cb);
        }
        cp_commit();
    };

    float o[8][4];
#pragma unroll
    for (int nt = 0; nt < 8; nt++)
#pragma unroll
        for (int e = 0; e < 4; e++) o[nt][e] = 0.0f;
    float m0 = -INFINITY, m1 = -INFINITY, l0 = 0.0f, l1 = 0.0f;

    stage_load(0, 0);

    for (int kv = 0; kv <= qtile; kv++) {
        const int s = kv & 1;
        if (kv < qtile) { stage_load(kv + 1, s ^ 1); cp_wait1(); }
        else            { cp_wait0(); }
        __syncthreads();

        const uint32_t skh = sbase + (uint32_t)s * STAGEB;
        const uint32_t skl = skh + KBYTES;
        const uint32_t svh = skh + 2 * KBYTES;
        const uint32_t svl = svh + VBYTES;
        const bool diag = (kv == qtile);

        // ---- S = Q K^T (split 3-mma) ----
        float cS[16][4];
#pragma unroll
        for (int j = 0; j < 16; j++)
#pragma unroll
            for (int e = 0; e < 4; e++) cS[j][e] = 0.0f;

#pragma unroll
        for (int kb = 0; kb < 4; kb++) {
#pragma unroll
            for (int jp = 0; jp < 8; jp++) {
                if (diag && jp > wid) continue;    // fully-masked col block
                const uint32_t koff = (jp * 16 + bRow) * (KPIT * 2) + kb * 32 + bCol;
                uint32_t th[4], tl[4];
                ldsm4(th, skh + koff);
                mma_bf16(cS[2*jp],   qfh[kb], th);
                mma_bf16(cS[2*jp],   qfl[kb], th);
                mma_bf16(cS[2*jp+1], qfh[kb], th + 2);
                mma_bf16(cS[2*jp+1], qfl[kb], th + 2);
                ldsm4(tl, skl + koff);
                mma_bf16(cS[2*jp],   qfh[kb], tl);
                mma_bf16(cS[2*jp+1], qfh[kb], tl + 2);
            }
        }

        // ---- scale + causal mask ----
        const int row0 = 16 * wid + g;
#pragma unroll
        for (int j = 0; j < 16; j++) {
            const int col0 = j * 8 + 2 * tig;
            cS[j][0] *= 0.125f; cS[j][1] *= 0.125f;
            cS[j][2] *= 0.125f; cS[j][3] *= 0.125f;
            if (diag) {
                if (col0     > row0)     cS[j][0] = -1e30f;
                if (col0 + 1 > row0)     cS[j][1] = -1e30f;
                if (col0     > row0 + 8) cS[j][2] = -1e30f;
                if (col0 + 1 > row0 + 8) cS[j][3] = -1e30f;
            }
        }

        // ---- online softmax ----
        float mx0 = -INFINITY, mx1 = -INFINITY;
#pragma unroll
        for (int j = 0; j < 16; j++) {
            mx0 = fmaxf(mx0, fmaxf(cS[j][0], cS[j][1]));
            mx1 = fmaxf(mx1, fmaxf(cS[j][2], cS[j][3]));
        }
        mx0 = fmaxf(mx0, __shfl_xor_sync(0xffffffffu, mx0, 1));
        mx0 = fmaxf(mx0, __shfl_xor_sync(0xffffffffu, mx0, 2));
        mx1 = fmaxf(mx1, __shfl_xor_sync(0xffffffffu, mx1, 1));
        mx1 = fmaxf(mx1, __shfl_xor_sync(0xffffffffu, mx1, 2));

        const float nm0 = fmaxf(m0, mx0), nm1 = fmaxf(m1, mx1);
        const float al0 = __expf(m0 - nm0), al1 = __expf(m1 - nm1);
        m0 = nm0; m1 = nm1;

        float rs0 = 0.0f, rs1 = 0.0f;
#pragma unroll
        for (int j = 0; j < 16; j++) {
            cS[j][0] = __expf(cS[j][0] - m0);
            cS[j][1] = __expf(cS[j][1] - m0);
            cS[j][2] = __expf(cS[j][2] - m1);
            cS[j][3] = __expf(cS[j][3] - m1);
            rs0 += cS[j][0] + cS[j][1];
            rs1 += cS[j][2] + cS[j][3];
        }
        rs0 += __shfl_xor_sync(0xffffffffu, rs0, 1);
        rs0 += __shfl_xor_sync(0xffffffffu, rs0, 2);
        rs1 += __shfl_xor_sync(0xffffffffu, rs1, 1);
        rs1 += __shfl_xor_sync(0xffffffffu, rs1, 2);
        l0 = l0 * al0 + rs0;
        l1 = l1 * al1 + rs1;

#pragma unroll
        for (int nt = 0; nt < 8; nt++) {
            o[nt][0] *= al0; o[nt][1] *= al0;
            o[nt][2] *= al1; o[nt][3] *= al1;
        }

        // ---- PV (skip zero P k-blocks on diag) ----
#pragma unroll
        for (int kb2 = 0; kb2 < 8; kb2++) {
            if (diag && kb2 > wid) continue;   // P identically zero there
            uint32_t aph[4], apl[4];
            split2(cS[2*kb2][0],   cS[2*kb2][1],   aph[0], apl[0]);
            split2(cS[2*kb2][2],   cS[2*kb2][3],   aph[1], apl[1]);
            split2(cS[2*kb2+1][0], cS[2*kb2+1][1], aph[2], apl[2]);
            split2(cS[2*kb2+1][2], cS[2*kb2+1][3], aph[3], apl[3]);
#pragma unroll
            for (int np = 0; np < 4; np++) {
                const uint32_t voff = (np * 16 + bRow) * (VPIT * 2) + kb2 * 32 + bCol;
                uint32_t th[4], tl[4];
                ldsm4(th, svh + voff);
                mma_bf16(o[2*np],   aph, th);
                mma_bf16(o[2*np],   apl, th);
                mma_bf16(o[2*np+1], aph, th + 2);
                mma_bf16(o[2*np+1], apl, th + 2);
                ldsm4(tl, svl + voff);
                mma_bf16(o[2*np],   aph, tl);
                mma_bf16(o[2*np+1], aph, tl + 2);
            }
        }
        __syncthreads();   // done reading stage s before it is re-staged
    }

    // ---- epilogue ----
    const int b = bh >> 4;
    const int h = bh & 15;
    const int t0 = qtile * 128 + 16 * wid + g;
    const float inv0 = 1.0f / l0, inv1 = 1.0f / l1;
#pragma unroll
    for (int nt = 0; nt < 8; nt++) {
        const int d = nt * 8 + 2 * tig;
        uint32_t ph, pl;
        split2(o[nt][0] * inv0, o[nt][1] * inv0, ph, pl);
        const size_t off0 = ((size_t)b * T_ + t0) * D_ + h * HD_ + d;
        *(uint32_t*)(g_atth + off0) = ph;
        *(uint32_t*)(g_attl + off0) = pl;
        split2(o[nt][2] * inv1, o[nt][3] * inv1, ph, pl);
        const size_t off1 = ((size_t)b * T_ + t0 + 8) * D_ + h * HD_ + d;
        *(uint32_t*)(g_atth + off1) = ph;
        *(uint32_t*)(g_attl + off1) = pl;
    }
}

// ---------------------------------------------------------------------------
extern "C" void kernel_launch(void* const* d_in, const int* in_sizes, int n_in,
                              void* d_out, int out_size)
{
    const float* x     = (const float*)d_in[0];
    // d_in[1] = mask (causal, static — ignored)
    const float* w_qkv = (const float*)d_in[2];
    const float* w_out = (const float*)d_in[3];
    float* out = (float*)d_out;

    cudaFuncSetAttribute(bgemm<0>, cudaFuncAttributeMaxDynamicSharedMemorySize, BGEMM_SMEM);
    cudaFuncSetAttribute(bgemm<1>, cudaFuncAttributeMaxDynamicSharedMemorySize, BGEMM_SMEM);
    cudaFuncSetAttribute(flash_tc, cudaFuncAttributeMaxDynamicSharedMemorySize, FLASH_SMEM);

    __nv_bfloat16 *xh, *xl, *wqh, *wql, *woh, *wol, *ath, *atl;
    cudaGetSymbolAddress((void**)&xh,  g_xh);     cudaGetSymbolAddress((void**)&xl,  g_xl);
    cudaGetSymbolAddress((void**)&wqh, g_wqkvTh); cudaGetSymbolAddress((void**)&wql, g_wqkvTl);
    cudaGetSymbolAddress((void**)&woh, g_woutTh); cudaGetSymbolAddress((void**)&wol, g_woutTl);
    cudaGetSymbolAddress((void**)&ath, g_atth);   cudaGetSymbolAddress((void**)&atl, g_attl);

    // 0) split x; split+transpose weights
    split4_kernel<<<(M_*D_/4 + 255)/256, 256>>>((const float4*)x,
        (__nv_bfloat162*)xh, (__nv_bfloat162*)xl, M_*D_/4);
    splitT_kernel<<<dim3(NQKV_/32, D_/32), dim3(32, 8)>>>(w_qkv, wqh, wql, D_, NQKV_);
    splitT_kernel<<<dim3(D_/32,  D_/32), dim3(32, 8)>>>(w_out, woh, wol, D_, D_);

    // 1) qkv = x @ w_qkv (tensor)
    bgemm<0><<<dim3(NQKV_/128, M_/128), 256, BGEMM_SMEM>>>(xh, xl, wqh, wql,
                                                           nullptr, NQKV_, K_);
    // 2) RoPE -> split bf16 q/k;  V -> transpose+split
    rope_kernel<<<(B_ * H_ * T_ * 32) / 256, 256>>>();
    vsplitT_kernel<<<dim3(T_/32, HD_/32, B_*H_), dim3(32, 8)>>>();

    // 3) tensor-core causal flash attention (double-buffered)
    flash_tc<<<dim3(T_ / 128, B_ * H_), 256, FLASH_SMEM>>>();

    // 4) out = att @ w_out (tensor)
    bgemm<1><<<dim3(D_/128, M_/128), 256, BGEMM_SMEM>>>(ath, atl, woh, wol,
                                                        out, D_, K_);
}

// round 12
// speedup vs baseline: 1.0339x; 1.0339x over previous
#include <cuda_runtime.h>
#include <cuda_bf16.h>
#include <math.h>
#include <stdint.h>

// Problem constants
#define B_   2
#define H_   16
#define T_   2048
#define D_   1024
#define HD_  64
#define M_   (B_*T_)      // 4096 rows
#define NQKV_ (3*D_)      // 3072
#define K_   1024

// Scratch (device globals: allocation-free rule)
__device__ float g_q[B_*H_*T_*HD_];   // fp32 pre-rope
__device__ float g_k[B_*H_*T_*HD_];
__device__ float g_v[B_*H_*T_*HD_];

// bf16 split operands
__device__ __align__(16) __nv_bfloat16 g_xh[M_*D_],    g_xl[M_*D_];
__device__ __align__(16) __nv_bfloat16 g_wqkvTh[NQKV_*D_], g_wqkvTl[NQKV_*D_];
__device__ __align__(16) __nv_bfloat16 g_woutTh[D_*D_],   g_woutTl[D_*D_];
__device__ __align__(16) __nv_bfloat16 g_atth[M_*D_],  g_attl[M_*D_];
__device__ __align__(16) __nv_bfloat16 g_qh[B_*H_*T_*HD_], g_ql[B_*H_*T_*HD_];  // [bh][t][d]
__device__ __align__(16) __nv_bfloat16 g_kh[B_*H_*T_*HD_], g_kl[B_*H_*T_*HD_];  // [bh][t][d]
__device__ __align__(16) __nv_bfloat16 g_vth[B_*H_*T_*HD_], g_vtl[B_*H_*T_*HD_]; // [bh][d][t]

__device__ __forceinline__ uint32_t smem_u32(const void* p) {
    uint32_t a;
    asm("{ .reg .u64 t; cvta.to.shared.u64 t, %1; cvt.u32.u64 %0, t; }" : "=r"(a) : "l"(p));
    return a;
}
__device__ __forceinline__ void cp_async16(uint32_t dst, const void* src) {
    asm volatile("cp.async.cg.shared.global [%0], [%1], 16;" :: "r"(dst), "l"(src));
}
__device__ __forceinline__ void cp_commit() { asm volatile("cp.async.commit_group;" ::: "memory"); }
__device__ __forceinline__ void cp_wait0()  { asm volatile("cp.async.wait_group 0;" ::: "memory"); }
__device__ __forceinline__ void ldsm4(uint32_t r[4], uint32_t addr) {
    asm volatile("ldmatrix.sync.aligned.m8n8.x4.shared.b16 {%0,%1,%2,%3}, [%4];"
        : "=r"(r[0]), "=r"(r[1]), "=r"(r[2]), "=r"(r[3]) : "r"(addr));
}
__device__ __forceinline__ void mma_bf16(float c[4], const uint32_t a[4], const uint32_t b[2]) {
    asm volatile(
        "mma.sync.aligned.m16n8k16.row.col.f32.bf16.bf16.f32 "
        "{%0,%1,%2,%3}, {%4,%5,%6,%7}, {%8,%9}, {%0,%1,%2,%3};"
        : "+f"(c[0]), "+f"(c[1]), "+f"(c[2]), "+f"(c[3])
        : "r"(a[0]), "r"(a[1]), "r"(a[2]), "r"(a[3]), "r"(b[0]), "r"(b[1]));
}
__device__ __forceinline__ void split1(float v, __nv_bfloat16& h, __nv_bfloat16& l) {
    h = __float2bfloat16(v);
    l = __float2bfloat16(v - __bfloat162float(h));
}
__device__ __forceinline__ void split2(float x, float y, uint32_t& h, uint32_t& l) {
    __nv_bfloat16 hx, lx, hy, ly;
    split1(x, hx, lx); split1(y, hy, ly);
    __nv_bfloat162 hv(hx, hy), lv(lx, ly);
    h = *(uint32_t*)&hv; l = *(uint32_t*)&lv;
}

// ---------------------------------------------------------------------------
// Feeders (unchanged)
// ---------------------------------------------------------------------------
__global__ void split4_kernel(const float4* __restrict__ src,
                              __nv_bfloat162* __restrict__ h,
                              __nv_bfloat162* __restrict__ l, int n4)
{
    const int i = blockIdx.x * blockDim.x + threadIdx.x;
    if (i >= n4) return;
    const float4 v = src[i];
    __nv_bfloat16 hx, lx, hy, ly, hz, lz, hw, lw;
    split1(v.x, hx, lx); split1(v.y, hy, ly);
    split1(v.z, hz, lz); split1(v.w, hw, lw);
    h[2*i]   = __nv_bfloat162(hx, hy);
    h[2*i+1] = __nv_bfloat162(hz, hw);
    l[2*i]   = __nv_bfloat162(lx, ly);
    l[2*i+1] = __nv_bfloat162(lz, lw);
}

__global__ void splitT_kernel(const float* __restrict__ src,
                              __nv_bfloat16* __restrict__ hT,
                              __nv_bfloat16* __restrict__ lT, int R, int C)
{
    __shared__ float tile[32][33];
    const int bx = blockIdx.x * 32, by = blockIdx.y * 32;
    const int tx = threadIdx.x, ty = threadIdx.y;
#pragma unroll
    for (int i = 0; i < 32; i += 8)
        tile[ty + i][tx] = src[(size_t)(by + ty + i) * C + bx + tx];
    __syncthreads();
#pragma unroll
    for (int i = 0; i < 32; i += 8) {
        const float v = tile[tx][ty + i];
        __nv_bfloat16 h, l;
        split1(v, h, l);
        const size_t o = (size_t)(bx + ty + i) * R + by + tx;
        hT[o] = h; lT[o] = l;
    }
}

__global__ void vsplitT_kernel()
{
    __shared__ float tile[32][33];
    const int bt = blockIdx.x * 32, bd = blockIdx.y * 32, bh = blockIdx.z;
    const int tx = threadIdx.x, ty = threadIdx.y;
    const float* src = g_v + (size_t)bh * T_ * HD_;
    __nv_bfloat16* dh = g_vth + (size_t)bh * HD_ * T_;
    __nv_bfloat16* dl = g_vtl + (size_t)bh * HD_ * T_;
#pragma unroll
    for (int i = 0; i < 32; i += 8)
        tile[ty + i][tx] = src[(size_t)(bt + ty + i) * HD_ + bd + tx];
    __syncthreads();
#pragma unroll
    for (int i = 0; i < 32; i += 8) {
        const float v = tile[tx][ty + i];
        __nv_bfloat16 h, l;
        split1(v, h, l);
        const size_t o = (size_t)(bd + ty + i) * T_ + bt + tx;
        dh[o] = h; dl[o] = l;
    }
}

// ---------------------------------------------------------------------------
// bf16 split-GEMM with ldmatrix fragment loading (unchanged from R10).
// ---------------------------------------------------------------------------
#define PB    40
#define MATB  (128 * PB * 2)
#define BUFB  (4 * MATB)
#define BGEMM_SMEM (2 * BUFB)

template<int MODE>
__global__ __launch_bounds__(256, 2)
void bgemm(const __nv_bfloat16* __restrict__ Ah, const __nv_bfloat16* __restrict__ Al,
           const __nv_bfloat16* __restrict__ Bh, const __nv_bfloat16* __restrict__ Bl,
           float* __restrict__ Cout, int N, int K)
{
    extern __shared__ char smc[];
    const uint32_t sb = smem_u32(smc);

    const int tid  = threadIdx.x;
    const int wid  = tid >> 5;
    const int lane = tid & 31;
    const int g    = lane >> 2;
    const int tig  = lane & 3;
    const int lq   = lane >> 3;
    const int lr   = lane & 7;
    const int warp_m = wid >> 2;
    const int warp_n = wid & 3;
    const int bm = blockIdx.y;
    const int bn = blockIdx.x;

    const char* gsrc[4] = {
        (const char*)(Ah + (size_t)bm * 128 * K),
        (const char*)(Al + (size_t)bm * 128 * K),
        (const char*)(Bh + (size_t)bn * 128 * K),
        (const char*)(Bl + (size_t)bn * 128 * K)
    };
    const size_t grs = (size_t)K * 2;

    float acc[4][4][4];
#pragma unroll
    for (int i = 0; i < 4; i++)
#pragma unroll
        for (int j = 0; j < 4; j++)
#pragma unroll
            for (int e = 0; e < 4; e++) acc[i][j][e] = 0.0f;

    const int NT = K / 32;

#pragma unroll
    for (int p = 0; p < 8; p++) {
        const int c   = tid + p * 256;
        const int mat = c >> 9;
        const int r   = (c >> 2) & 127;
        const int q   = (c & 3) * 16;
        cp_async16(sb + mat * MATB + r * (PB * 2) + q,
                   gsrc[mat] + (size_t)r * grs + q);
    }
    cp_commit();
    cp_wait0();
    __syncthreads();

    const uint32_t aRow = lr + (lq & 1) * 8;
    const uint32_t aCol = (lq >> 1) * 16;
    const uint32_t bRow = lr + (lq >> 1) * 8;
    const uint32_t bCol = (lq & 1) * 16;

    for (int t = 0; t < NT; t++) {
        const int buf = t & 1;

        if (t + 1 < NT) {
            const uint32_t db = sb + (buf ^ 1) * BUFB;
            const size_t kb = (size_t)(t + 1) * 64;
#pragma unroll
            for (int p = 0; p < 8; p++) {
                const int c   = tid + p * 256;
                const int mat = c >> 9;
                const int r   = (c >> 2) & 127;
                const int q   = (c & 3) * 16;
                cp_async16(db + mat * MATB + r * (PB * 2) + q,
                           gsrc[mat] + (size_t)r * grs + kb + q);
            }
            cp_commit();
        }

        const uint32_t base = sb + buf * BUFB;
#pragma unroll
        for (int ks = 0; ks < 2; ks++) {
            const uint32_t ko = ks * 32;

            uint32_t ah[4][4], al[4][4], bh[4][2], bl[4][2];
#pragma unroll
            for (int i = 0; i < 4; i++) {
                const uint32_t ao = (warp_m * 64 + i * 16 + aRow) * (PB * 2) + ko + aCol;
                ldsm4(ah[i], base + ao);
                ldsm4(al[i], base + MATB + ao);
            }
#pragma unroll
            for (int jp = 0; jp < 2; jp++) {
                const uint32_t bo = (warp_n * 32 + jp * 16 + bRow) * (PB * 2) + ko + bCol;
                uint32_t th[4], tl[4];
                ldsm4(th, base + 2 * MATB + bo);
                bh[2*jp][0] = th[0]; bh[2*jp][1] = th[1];
                bh[2*jp+1][0] = th[2]; bh[2*jp+1][1] = th[3];
                ldsm4(tl, base + 3 * MATB + bo);
                bl[2*jp][0] = tl[0]; bl[2*jp][1] = tl[1];
                bl[2*jp+1][0] = tl[2]; bl[2*jp+1][1] = tl[3];
            }

#pragma unroll
            for (int i = 0; i < 4; i++)
#pragma unroll
                for (int j = 0; j < 4; j++)
                    mma_bf16(acc[i][j], ah[i], bh[j]);
#pragma unroll
            for (int i = 0; i < 4; i++)
#pragma unroll
                for (int j = 0; j < 4; j++)
                    mma_bf16(acc[i][j], al[i], bh[j]);
#pragma unroll
            for (int i = 0; i < 4; i++)
#pragma unroll
                for (int j = 0; j < 4; j++)
                    mma_bf16(acc[i][j], ah[i], bl[j]);
        }

        if (t + 1 < NT) cp_wait0();
        __syncthreads();
    }

#pragma unroll
    for (int i = 0; i < 4; i++) {
        const int r0 = bm * 128 + warp_m * 64 + i * 16 + g;
#pragma unroll
        for (int j = 0; j < 4; j++) {
            const int c0 = bn * 128 + warp_n * 32 + j * 8 + tig * 2;
#pragma unroll
            for (int half = 0; half < 2; half++) {
                const int r = r0 + half * 8;
                const float2 v = make_float2(acc[i][j][half * 2], acc[i][j][half * 2 + 1]);
                if (MODE == 0) {
                    const int b    = r >> 11;
                    const int tt   = r & (T_ - 1);
                    const int part = c0 >> 10;
                    const int idx  = c0 & 1023;
                    const int h    = idx >> 6;
                    const int d    = idx & 63;
                    float* dst = (part == 0) ? g_q : (part == 1) ? g_k : g_v;
                    *(float2*)(dst + (((size_t)b * H_ + h) * T_ + tt) * HD_ + d) = v;
                } else {
                    *(float2*)(Cout + (size_t)r * N + c0) = v;
                }
            }
        }
    }
}

// ---------------------------------------------------------------------------
// RoPE (unchanged): fp32 q/k -> split bf16
// ---------------------------------------------------------------------------
__global__ void rope_kernel()
{
    const int idx = blockIdx.x * blockDim.x + threadIdx.x;
    const int j  = idx & 31;
    const int t  = (idx >> 5) & (T_ - 1);
    const int bh = idx >> 16;

    const float f = exp2f(-(float)j * (13.287712379549449f / 32.0f));
    float s, c;
    sincosf((float)t * f, &s, &c);

    const size_t base = ((size_t)bh * T_ + t) * HD_;
    float a0 = g_q[base + j], b0 = g_q[base + j + 32];
    float a1 = g_k[base + j], b1 = g_k[base + j + 32];
    const float q0 = a0 * c - b0 * s, q1 = b0 * c + a0 * s;
    const float k0 = a1 * c - b1 * s, k1 = b1 * c + a1 * s;
    __nv_bfloat16 h, l;
    split1(q0, h, l); g_qh[base + j] = h;      g_ql[base + j] = l;
    split1(q1, h, l); g_qh[base + j + 32] = h; g_ql[base + j + 32] = l;
    split1(k0, h, l); g_kh[base + j] = h;      g_kl[base + j] = l;
    split1(k1, h, l); g_kh[base + j + 32] = h; g_kl[base + j + 32] = l;
}

// ---------------------------------------------------------------------------
// Tensor-core flash attention (R10 structure: single buffer, 2 CTA/SM)
// + causal diag-tile mma skips (validated in R11).
// ---------------------------------------------------------------------------
#define KPIT 72
#define VPIT 136
#define SM_KH 0
#define SM_KL (128 * KPIT)
#define SM_VH (2 * 128 * KPIT)
#define SM_VL (2 * 128 * KPIT + 64 * VPIT)
#define FLASH_SMEM ((2 * 128 * KPIT + 2 * 64 * VPIT) * 2)   // 71680 B

__global__ __launch_bounds__(256, 1)
void flash_tc()
{
    extern __shared__ __nv_bfloat16 smb[];
    __nv_bfloat16* Karr[2] = { smb + SM_KH, smb + SM_KL };
    __nv_bfloat16* Varr[2] = { smb + SM_VH, smb + SM_VL };
    const uint32_t skh = smem_u32(smb + SM_KH);
    const uint32_t skl = smem_u32(smb + SM_KL);
    const uint32_t svh = smem_u32(smb + SM_VH);
    const uint32_t svl = smem_u32(smb + SM_VL);

    const int tid  = threadIdx.x;
    const int wid  = tid >> 5;
    const int lane = tid & 31;
    const int g    = lane >> 2;
    const int tig  = lane & 3;
    const int lq   = lane >> 3;
    const int lr   = lane & 7;
    const int qtile = (int)gridDim.x - 1 - (int)blockIdx.x;
    const int bh    = blockIdx.y;

    const size_t qkbase = ((size_t)bh * T_ + (size_t)qtile * 128) * HD_;
    const size_t kvrow0 = (size_t)bh * T_ * HD_;
    const size_t vtbase = (size_t)bh * HD_ * T_;

    const uint32_t aRow = lr + (lq & 1) * 8;
    const uint32_t aCol = (lq >> 1) * 16;
    const uint32_t bRow = lr + (lq >> 1) * 8;
    const uint32_t bCol = (lq & 1) * 16;

    // ---- stage Q, extract A-fragments via ldmatrix, release smem ----
    {
        const __nv_bfloat16* qsrc[2] = { g_qh + qkbase, g_ql + qkbase };
#pragma unroll
        for (int p = 0; p < 8; p++) {
            const int c   = tid + p * 256;
            const int mat = c >> 10;
            const int rem = c & 1023;
            const int r   = rem >> 3;
            const int c8  = (rem & 7) * 8;
            *(uint4*)(Karr[mat] + r * KPIT + c8) =
                *(const uint4*)(qsrc[mat] + r * HD_ + c8);
        }
    }
    __syncthreads();

    uint32_t qfh[4][4], qfl[4][4];
#pragma unroll
    for (int kb = 0; kb < 4; kb++) {
        const uint32_t qo = (16 * wid + aRow) * (KPIT * 2) + kb * 32 + aCol;
        ldsm4(qfh[kb], skh + qo);
        ldsm4(qfl[kb], skl + qo);
    }

    float o[8][4];
#pragma unroll
    for (int nt = 0; nt < 8; nt++)
#pragma unroll
        for (int e = 0; e < 4; e++) o[nt][e] = 0.0f;
    float m0 = -INFINITY, m1 = -INFINITY, l0 = 0.0f, l1 = 0.0f;

    for (int kv = 0; kv <= qtile; kv++) {
        __syncthreads();
        {
            const __nv_bfloat16* ksrc[2] = { g_kh + kvrow0 + (size_t)kv * 128 * HD_,
                                             g_kl + kvrow0 + (size_t)kv * 128 * HD_ };
            const __nv_bfloat16* vsrc[2] = { g_vth + vtbase + (size_t)kv * 128,
                                             g_vtl + vtbase + (size_t)kv * 128 };
#pragma unroll
            for (int p = 0; p < 8; p++) {
                const int c   = tid + p * 256;
                const int mat = c >> 10;
                const int rem = c & 1023;
                const int r   = rem >> 3;
                const int c8  = (rem & 7) * 8;
                *(uint4*)(Karr[mat] + r * KPIT + c8) =
                    *(const uint4*)(ksrc[mat] + r * HD_ + c8);
            }
#pragma unroll
            for (int p = 0; p < 8; p++) {
                const int c   = tid + p * 256;
                const int mat = c >> 10;
                const int rem = c & 1023;
                const int d   = rem >> 4;
                const int c8  = (rem & 15) * 8;
                *(uint4*)(Varr[mat] + d * VPIT + c8) =
                    *(const uint4*)(vsrc[mat] + (size_t)d * T_ + c8);
            }
        }
        __syncthreads();

        const bool diag = (kv == qtile);

        // ---- S = Q K^T (split 3-mma, diag-skip fully-masked col blocks) ----
        float cS[16][4];
#pragma unroll
        for (int j = 0; j < 16; j++)
#pragma unroll
            for (int e = 0; e < 4; e++) cS[j][e] = 0.0f;

#pragma unroll
        for (int kb = 0; kb < 4; kb++) {
#pragma unroll
            for (int jp = 0; jp < 8; jp++) {
                if (diag && jp > wid) continue;
                const uint32_t koff = (jp * 16 + bRow) * (KPIT * 2) + kb * 32 + bCol;
                uint32_t th[4], tl[4];
                ldsm4(th, skh + koff);
                mma_bf16(cS[2*jp],   qfh[kb], th);
                mma_bf16(cS[2*jp],   qfl[kb], th);
                mma_bf16(cS[2*jp+1], qfh[kb], th + 2);
                mma_bf16(cS[2*jp+1], qfl[kb], th + 2);
                ldsm4(tl, skl + koff);
                mma_bf16(cS[2*jp],   qfh[kb], tl);
                mma_bf16(cS[2*jp+1], qfh[kb], tl + 2);
            }
        }

        // ---- scale + causal mask ----
        const int row0 = 16 * wid + g;
#pragma unroll
        for (int j = 0; j < 16; j++) {
            const int col0 = j * 8 + 2 * tig;
            cS[j][0] *= 0.125f; cS[j][1] *= 0.125f;
            cS[j][2] *= 0.125f; cS[j][3] *= 0.125f;
            if (diag) {
                if (col0     > row0)     cS[j][0] = -1e30f;
                if (col0 + 1 > row0)     cS[j][1] = -1e30f;
                if (col0     > row0 + 8) cS[j][2] = -1e30f;
                if (col0 + 1 > row0 + 8) cS[j][3] = -1e30f;
            }
        }

        // ---- online softmax ----
        float mx0 = -INFINITY, mx1 = -INFINITY;
#pragma unroll
        for (int j = 0; j < 16; j++) {
            mx0 = fmaxf(mx0, fmaxf(cS[j][0], cS[j][1]));
            mx1 = fmaxf(mx1, fmaxf(cS[j][2], cS[j][3]));
        }
        mx0 = fmaxf(mx0, __shfl_xor_sync(0xffffffffu, mx0, 1));
        mx0 = fmaxf(mx0, __shfl_xor_sync(0xffffffffu, mx0, 2));
        mx1 = fmaxf(mx1, __shfl_xor_sync(0xffffffffu, mx1, 1));
        mx1 = fmaxf(mx1, __shfl_xor_sync(0xffffffffu, mx1, 2));

        const float nm0 = fmaxf(m0, mx0), nm1 = fmaxf(m1, mx1);
        const float al0 = __expf(m0 - nm0), al1 = __expf(m1 - nm1);
        m0 = nm0; m1 = nm1;

        float rs0 = 0.0f, rs1 = 0.0f;
#pragma unroll
        for (int j = 0; j < 16; j++) {
            cS[j][0] = __expf(cS[j][0] - m0);
            cS[j][1] = __expf(cS[j][1] - m0);
            cS[j][2] = __expf(cS[j][2] - m1);
            cS[j][3] = __expf(cS[j][3] - m1);
            rs0 += cS[j][0] + cS[j][1];
            rs1 += cS[j][2] + cS[j][3];
        }
        rs0 += __shfl_xor_sync(0xffffffffu, rs0, 1);
        rs0 += __shfl_xor_sync(0xffffffffu, rs0, 2);
        rs1 += __shfl_xor_sync(0xffffffffu, rs1, 1);
        rs1 += __shfl_xor_sync(0xffffffffu, rs1, 2);
        l0 = l0 * al0 + rs0;
        l1 = l1 * al1 + rs1;

#pragma unroll
        for (int nt = 0; nt < 8; nt++) {
            o[nt][0] *= al0; o[nt][1] *= al0;
            o[nt][2] *= al1; o[nt][3] *= al1;
        }

        // ---- PV (skip zero P k-blocks on diag) ----
#pragma unroll
        for (int kb2 = 0; kb2 < 8; kb2++) {
            if (diag && kb2 > wid) continue;
            uint32_t aph[4], apl[4];
            split2(cS[2*kb2][0],   cS[2*kb2][1],   aph[0], apl[0]);
            split2(cS[2*kb2][2],   cS[2*kb2][3],   aph[1], apl[1]);
            split2(cS[2*kb2+1][0], cS[2*kb2+1][1], aph[2], apl[2]);
            split2(cS[2*kb2+1][2], cS[2*kb2+1][3], aph[3], apl[3]);
#pragma unroll
            for (int np = 0; np < 4; np++) {
                const uint32_t voff = (np * 16 + bRow) * (VPIT * 2) + kb2 * 32 + bCol;
                uint32_t th[4], tl[4];
                ldsm4(th, svh + voff);
                mma_bf16(o[2*np],   aph, th);
                mma_bf16(o[2*np],   apl, th);
                mma_bf16(o[2*np+1], aph, th + 2);
                mma_bf16(o[2*np+1], apl, th + 2);
                ldsm4(tl, svl + voff);
                mma_bf16(o[2*np],   aph, tl);
                mma_bf16(o[2*np+1], aph, tl + 2);
            }
        }
    }

    // ---- epilogue ----
    const int b = bh >> 4;
    const int h = bh & 15;
    const int t0 = qtile * 128 + 16 * wid + g;
    const float inv0 = 1.0f / l0, inv1 = 1.0f / l1;
#pragma unroll
    for (int nt = 0; nt < 8; nt++) {
        const int d = nt * 8 + 2 * tig;
        uint32_t ph, pl;
        split2(o[nt][0] * inv0, o[nt][1] * inv0, ph, pl);
        const size_t off0 = ((size_t)b * T_ + t0) * D_ + h * HD_ + d;
        *(uint32_t*)(g_atth + off0) = ph;
        *(uint32_t*)(g_attl + off0) = pl;
        split2(o[nt][2] * inv1, o[nt][3] * inv1, ph, pl);
        const size_t off1 = ((size_t)b * T_ + t0 + 8) * D_ + h * HD_ + d;
        *(uint32_t*)(g_atth + off1) = ph;
        *(uint32_t*)(g_attl + off1) = pl;
    }
}

// ---------------------------------------------------------------------------
extern "C" void kernel_launch(void* const* d_in, const int* in_sizes, int n_in,
                              void* d_out, int out_size)
{
    const float* x     = (const float*)d_in[0];
    // d_in[1] = mask (causal, static — ignored)
    const float* w_qkv = (const float*)d_in[2];
    const float* w_out = (const float*)d_in[3];
    float* out = (float*)d_out;

    cudaFuncSetAttribute(bgemm<0>, cudaFuncAttributeMaxDynamicSharedMemorySize, BGEMM_SMEM);
    cudaFuncSetAttribute(bgemm<1>, cudaFuncAttributeMaxDynamicSharedMemorySize, BGEMM_SMEM);
    cudaFuncSetAttribute(flash_tc, cudaFuncAttributeMaxDynamicSharedMemorySize, FLASH_SMEM);

    __nv_bfloat16 *xh, *xl, *wqh, *wql, *woh, *wol, *ath, *atl;
    cudaGetSymbolAddress((void**)&xh,  g_xh);     cudaGetSymbolAddress((void**)&xl,  g_xl);
    cudaGetSymbolAddress((void**)&wqh, g_wqkvTh); cudaGetSymbolAddress((void**)&wql, g_wqkvTl);
    cudaGetSymbolAddress((void**)&woh, g_woutTh); cudaGetSymbolAddress((void**)&wol, g_woutTl);
    cudaGetSymbolAddress((void**)&ath, g_atth);   cudaGetSymbolAddress((void**)&atl, g_attl);

    // 0) split x; split+transpose weights
    split4_kernel<<<(M_*D_/4 + 255)/256, 256>>>((const float4*)x,
        (__nv_bfloat162*)xh, (__nv_bfloat162*)xl, M_*D_/4);
    splitT_kernel<<<dim3(NQKV_/32, D_/32), dim3(32, 8)>>>(w_qkv, wqh, wql, D_, NQKV_);
    splitT_kernel<<<dim3(D_/32,  D_/32), dim3(32, 8)>>>(w_out, woh, wol, D_, D_);

    // 1) qkv = x @ w_qkv (tensor)
    bgemm<0><<<dim3(NQKV_/128, M_/128), 256, BGEMM_SMEM>>>(xh, xl, wqh, wql,
                                                           nullptr, NQKV_, K_);
    // 2) RoPE -> split bf16 q/k;  V -> transpose+split
    rope_kernel<<<(B_ * H_ * T_ * 32) / 256, 256>>>();
    vsplitT_kernel<<<dim3(T_/32, HD_/32, B_*H_), dim3(32, 8)>>>();

    // 3) tensor-core causal flash attention (single buffer, 2 CTA/SM)
    flash_tc<<<dim3(T_ / 128, B_ * H_), 256, FLASH_SMEM>>>();

    // 4) out = att @ w_out (tensor)
    bgemm<1><<<dim3(D_/128, M_/128), 256, BGEMM_SMEM>>>(ath, atl, woh, wol,
                                                        out, D_, K_);
}

// round 13
// speedup vs baseline: 1.0632x; 1.0283x over previous
#include <cuda_runtime.h>
#include <cuda_bf16.h>
#include <math.h>
#include <stdint.h>

// Problem constants
#define B_   2
#define H_   16
#define T_   2048
#define D_   1024
#define HD_  64
#define M_   (B_*T_)      // 4096 rows
#define NQKV_ (3*D_)      // 3072
#define K_   1024

// Scratch (device globals: allocation-free rule)
__device__ float g_q[B_*H_*T_*HD_];   // fp32 pre-rope
__device__ float g_k[B_*H_*T_*HD_];
__device__ float g_v[B_*H_*T_*HD_];

// bf16 split operands
__device__ __align__(16) __nv_bfloat16 g_xh[M_*D_],    g_xl[M_*D_];
__device__ __align__(16) __nv_bfloat16 g_wqkvTh[NQKV_*D_], g_wqkvTl[NQKV_*D_];
__device__ __align__(16) __nv_bfloat16 g_woutTh[D_*D_],   g_woutTl[D_*D_];
__device__ __align__(16) __nv_bfloat16 g_atth[M_*D_],  g_attl[M_*D_];
__device__ __align__(16) __nv_bfloat16 g_qh[B_*H_*T_*HD_], g_ql[B_*H_*T_*HD_];  // [bh][t][d]
__device__ __align__(16) __nv_bfloat16 g_kh[B_*H_*T_*HD_], g_kl[B_*H_*T_*HD_];  // [bh][t][d]
__device__ __align__(16) __nv_bfloat16 g_vth[B_*H_*T_*HD_], g_vtl[B_*H_*T_*HD_]; // [bh][d][t]

__device__ __forceinline__ uint32_t smem_u32(const void* p) {
    uint32_t a;
    asm("{ .reg .u64 t; cvta.to.shared.u64 t, %1; cvt.u32.u64 %0, t; }" : "=r"(a) : "l"(p));
    return a;
}
__device__ __forceinline__ void cp_async16(uint32_t dst, const void* src) {
    asm volatile("cp.async.cg.shared.global [%0], [%1], 16;" :: "r"(dst), "l"(src));
}
__device__ __forceinline__ void cp_commit() { asm volatile("cp.async.commit_group;" ::: "memory"); }
__device__ __forceinline__ void cp_wait0()  { asm volatile("cp.async.wait_group 0;" ::: "memory"); }
__device__ __forceinline__ void ldsm4(uint32_t r[4], uint32_t addr) {
    asm volatile("ldmatrix.sync.aligned.m8n8.x4.shared.b16 {%0,%1,%2,%3}, [%4];"
        : "=r"(r[0]), "=r"(r[1]), "=r"(r[2]), "=r"(r[3]) : "r"(addr));
}
__device__ __forceinline__ void mma_bf16(float c[4], const uint32_t a[4], const uint32_t b[2]) {
    asm volatile(
        "mma.sync.aligned.m16n8k16.row.col.f32.bf16.bf16.f32 "
        "{%0,%1,%2,%3}, {%4,%5,%6,%7}, {%8,%9}, {%0,%1,%2,%3};"
        : "+f"(c[0]), "+f"(c[1]), "+f"(c[2]), "+f"(c[3])
        : "r"(a[0]), "r"(a[1]), "r"(a[2]), "r"(a[3]), "r"(b[0]), "r"(b[1]));
}
__device__ __forceinline__ void split1(float v, __nv_bfloat16& h, __nv_bfloat16& l) {
    h = __float2bfloat16(v);
    l = __float2bfloat16(v - __bfloat162float(h));
}
__device__ __forceinline__ void split2(float x, float y, uint32_t& h, uint32_t& l) {
    __nv_bfloat16 hx, lx, hy, ly;
    split1(x, hx, lx); split1(y, hy, ly);
    __nv_bfloat162 hv(hx, hy), lv(lx, ly);
    h = *(uint32_t*)&hv; l = *(uint32_t*)&lv;
}

// ---------------------------------------------------------------------------
// Feeders
// ---------------------------------------------------------------------------
__global__ void split4_kernel(const float4* __restrict__ src,
                              __nv_bfloat162* __restrict__ h,
                              __nv_bfloat162* __restrict__ l, int n4)
{
    const int i = blockIdx.x * blockDim.x + threadIdx.x;
    if (i >= n4) return;
    const float4 v = src[i];
    __nv_bfloat16 hx, lx, hy, ly, hz, lz, hw, lw;
    split1(v.x, hx, lx); split1(v.y, hy, ly);
    split1(v.z, hz, lz); split1(v.w, hw, lw);
    h[2*i]   = __nv_bfloat162(hx, hy);
    h[2*i+1] = __nv_bfloat162(hz, hw);
    l[2*i]   = __nv_bfloat162(lx, ly);
    l[2*i+1] = __nv_bfloat162(lz, lw);
}

__global__ void splitT_kernel(const float* __restrict__ src,
                              __nv_bfloat16* __restrict__ hT,
                              __nv_bfloat16* __restrict__ lT, int R, int C)
{
    __shared__ float tile[32][33];
    const int bx = blockIdx.x * 32, by = blockIdx.y * 32;
    const int tx = threadIdx.x, ty = threadIdx.y;
#pragma unroll
    for (int i = 0; i < 32; i += 8)
        tile[ty + i][tx] = src[(size_t)(by + ty + i) * C + bx + tx];
    __syncthreads();
#pragma unroll
    for (int i = 0; i < 32; i += 8) {
        const float v = tile[tx][ty + i];
        __nv_bfloat16 h, l;
        split1(v, h, l);
        const size_t o = (size_t)(bx + ty + i) * R + by + tx;
        hT[o] = h; lT[o] = l;
    }
}

// vsplitT with paired (4B) stores: per-bh transpose+split g_v -> g_vth/l [bh][d][t]
__global__ void vsplitT_kernel()
{
    __shared__ float tile[32][33];   // tile[t_local][d_local]
    const int bt = blockIdx.x * 32, bd = blockIdx.y * 32, bh = blockIdx.z;
    const int tx = threadIdx.x, ty = threadIdx.y;   // 32 x 8
    const int tid = ty * 32 + tx;                    // 0..255
    const float* src = g_v + (size_t)bh * T_ * HD_;
    __nv_bfloat16* dh = g_vth + (size_t)bh * HD_ * T_;
    __nv_bfloat16* dl = g_vtl + (size_t)bh * HD_ * T_;
#pragma unroll
    for (int i = 0; i < 32; i += 8)
        tile[ty + i][tx] = src[(size_t)(bt + ty + i) * HD_ + bd + tx];
    __syncthreads();
    // 32 d-rows x 16 t-pairs = 512 items, 2 per thread; stores are 4B
#pragma unroll
    for (int w = 0; w < 2; w++) {
        const int item = tid + w * 256;
        const int drow = item >> 4;          // 0..31
        const int tp   = item & 15;          // t-pair 0..15
        const float v0 = tile[2 * tp][drow];
        const float v1 = tile[2 * tp + 1][drow];
        uint32_t ph, pl;
        split2(v0, v1, ph, pl);
        const size_t o = (size_t)(bd + drow) * T_ + bt + 2 * tp;
        *(uint32_t*)(dh + o) = ph;
        *(uint32_t*)(dl + o) = pl;
    }
}

// ---------------------------------------------------------------------------
// bf16 split-GEMM with ldmatrix fragment loading (unchanged from R10).
// ---------------------------------------------------------------------------
#define PB    40
#define MATB  (128 * PB * 2)
#define BUFB  (4 * MATB)
#define BGEMM_SMEM (2 * BUFB)

template<int MODE>
__global__ __launch_bounds__(256, 2)
void bgemm(const __nv_bfloat16* __restrict__ Ah, const __nv_bfloat16* __restrict__ Al,
           const __nv_bfloat16* __restrict__ Bh, const __nv_bfloat16* __restrict__ Bl,
           float* __restrict__ Cout, int N, int K)
{
    extern __shared__ char smc[];
    const uint32_t sb = smem_u32(smc);

    const int tid  = threadIdx.x;
    const int wid  = tid >> 5;
    const int lane = tid & 31;
    const int g    = lane >> 2;
    const int tig  = lane & 3;
    const int lq   = lane >> 3;
    const int lr   = lane & 7;
    const int warp_m = wid >> 2;
    const int warp_n = wid & 3;
    const int bm = blockIdx.y;
    const int bn = blockIdx.x;

    const char* gsrc[4] = {
        (const char*)(Ah + (size_t)bm * 128 * K),
        (const char*)(Al + (size_t)bm * 128 * K),
        (const char*)(Bh + (size_t)bn * 128 * K),
        (const char*)(Bl + (size_t)bn * 128 * K)
    };
    const size_t grs = (size_t)K * 2;

    float acc[4][4][4];
#pragma unroll
    for (int i = 0; i < 4; i++)
#pragma unroll
        for (int j = 0; j < 4; j++)
#pragma unroll
            for (int e = 0; e < 4; e++) acc[i][j][e] = 0.0f;

    const int NT = K / 32;

#pragma unroll
    for (int p = 0; p < 8; p++) {
        const int c   = tid + p * 256;
        const int mat = c >> 9;
        const int r   = (c >> 2) & 127;
        const int q   = (c & 3) * 16;
        cp_async16(sb + mat * MATB + r * (PB * 2) + q,
                   gsrc[mat] + (size_t)r * grs + q);
    }
    cp_commit();
    cp_wait0();
    __syncthreads();

    const uint32_t aRow = lr + (lq & 1) * 8;
    const uint32_t aCol = (lq >> 1) * 16;
    const uint32_t bRow = lr + (lq >> 1) * 8;
    const uint32_t bCol = (lq & 1) * 16;

    for (int t = 0; t < NT; t++) {
        const int buf = t & 1;

        if (t + 1 < NT) {
            const uint32_t db = sb + (buf ^ 1) * BUFB;
            const size_t kb = (size_t)(t + 1) * 64;
#pragma unroll
            for (int p = 0; p < 8; p++) {
                const int c   = tid + p * 256;
                const int mat = c >> 9;
                const int r   = (c >> 2) & 127;
                const int q   = (c & 3) * 16;
                cp_async16(db + mat * MATB + r * (PB * 2) + q,
                           gsrc[mat] + (size_t)r * grs + kb + q);
            }
            cp_commit();
        }

        const uint32_t base = sb + buf * BUFB;
#pragma unroll
        for (int ks = 0; ks < 2; ks++) {
            const uint32_t ko = ks * 32;

            uint32_t ah[4][4], al[4][4], bh[4][2], bl[4][2];
#pragma unroll
            for (int i = 0; i < 4; i++) {
                const uint32_t ao = (warp_m * 64 + i * 16 + aRow) * (PB * 2) + ko + aCol;
                ldsm4(ah[i], base + ao);
                ldsm4(al[i], base + MATB + ao);
            }
#pragma unroll
            for (int jp = 0; jp < 2; jp++) {
                const uint32_t bo = (warp_n * 32 + jp * 16 + bRow) * (PB * 2) + ko + bCol;
                uint32_t th[4], tl[4];
                ldsm4(th, base + 2 * MATB + bo);
                bh[2*jp][0] = th[0]; bh[2*jp][1] = th[1];
                bh[2*jp+1][0] = th[2]; bh[2*jp+1][1] = th[3];
                ldsm4(tl, base + 3 * MATB + bo);
                bl[2*jp][0] = tl[0]; bl[2*jp][1] = tl[1];
                bl[2*jp+1][0] = tl[2]; bl[2*jp+1][1] = tl[3];
            }

#pragma unroll
            for (int i = 0; i < 4; i++)
#pragma unroll
                for (int j = 0; j < 4; j++)
                    mma_bf16(acc[i][j], ah[i], bh[j]);
#pragma unroll
            for (int i = 0; i < 4; i++)
#pragma unroll
                for (int j = 0; j < 4; j++)
                    mma_bf16(acc[i][j], al[i], bh[j]);
#pragma unroll
            for (int i = 0; i < 4; i++)
#pragma unroll
                for (int j = 0; j < 4; j++)
                    mma_bf16(acc[i][j], ah[i], bl[j]);
        }

        if (t + 1 < NT) cp_wait0();
        __syncthreads();
    }

#pragma unroll
    for (int i = 0; i < 4; i++) {
        const int r0 = bm * 128 + warp_m * 64 + i * 16 + g;
#pragma unroll
        for (int j = 0; j < 4; j++) {
            const int c0 = bn * 128 + warp_n * 32 + j * 8 + tig * 2;
#pragma unroll
            for (int half = 0; half < 2; half++) {
                const int r = r0 + half * 8;
                const float2 v = make_float2(acc[i][j][half * 2], acc[i][j][half * 2 + 1]);
                if (MODE == 0) {
                    const int b    = r >> 11;
                    const int tt   = r & (T_ - 1);
                    const int part = c0 >> 10;
                    const int idx  = c0 & 1023;
                    const int h    = idx >> 6;
                    const int d    = idx & 63;
                    float* dst = (part == 0) ? g_q : (part == 1) ? g_k : g_v;
                    *(float2*)(dst + (((size_t)b * H_ + h) * T_ + tt) * HD_ + d) = v;
                } else {
                    *(float2*)(Cout + (size_t)r * N + c0) = v;
                }
            }
        }
    }
}

// ---------------------------------------------------------------------------
// RoPE with paired (4B) stores: fp32 q/k -> split bf16. Thread handles j pair.
// grid: B*H*T*16 threads
// ---------------------------------------------------------------------------
__global__ void rope_kernel()
{
    const int idx = blockIdx.x * blockDim.x + threadIdx.x;
    const int j2 = idx & 15;                 // j-pair index
    const int t  = (idx >> 4) & (T_ - 1);
    const int bh = idx >> 15;

    const float tf = (float)t;
    const size_t base = ((size_t)bh * T_ + t) * HD_;

    float q0[2], q1[2], k0[2], k1[2];
#pragma unroll
    for (int u = 0; u < 2; u++) {
        const int j = 2 * j2 + u;
        const float f = exp2f(-(float)j * (13.287712379549449f / 32.0f));
        float s, c;
        sincosf(tf * f, &s, &c);
        const float a0 = g_q[base + j], b0 = g_q[base + j + 32];
        const float a1 = g_k[base + j], b1 = g_k[base + j + 32];
        q0[u] = a0 * c - b0 * s;  q1[u] = b0 * c + a0 * s;
        k0[u] = a1 * c - b1 * s;  k1[u] = b1 * c + a1 * s;
    }

    uint32_t ph, pl;
    split2(q0[0], q0[1], ph, pl);
    *(uint32_t*)(g_qh + base + 2 * j2) = ph;      *(uint32_t*)(g_ql + base + 2 * j2) = pl;
    split2(q1[0], q1[1], ph, pl);
    *(uint32_t*)(g_qh + base + 2 * j2 + 32) = ph; *(uint32_t*)(g_ql + base + 2 * j2 + 32) = pl;
    split2(k0[0], k0[1], ph, pl);
    *(uint32_t*)(g_kh + base + 2 * j2) = ph;      *(uint32_t*)(g_kl + base + 2 * j2) = pl;
    split2(k1[0], k1[1], ph, pl);
    *(uint32_t*)(g_kh + base + 2 * j2 + 32) = ph; *(uint32_t*)(g_kl + base + 2 * j2 + 32) = pl;
}

// ---------------------------------------------------------------------------
// Tensor-core flash attention — EXACT R10 structure (single buffer, 2 CTA/SM,
// no diag skips).
// ---------------------------------------------------------------------------
#define KPIT 72
#define VPIT 136
#define SM_KH 0
#define SM_KL (128 * KPIT)
#define SM_VH (2 * 128 * KPIT)
#define SM_VL (2 * 128 * KPIT + 64 * VPIT)
#define FLASH_SMEM ((2 * 128 * KPIT + 2 * 64 * VPIT) * 2)

__global__ __launch_bounds__(256, 1)
void flash_tc()
{
    extern __shared__ __nv_bfloat16 smb[];
    __nv_bfloat16* Karr[2] = { smb + SM_KH, smb + SM_KL };
    __nv_bfloat16* Varr[2] = { smb + SM_VH, smb + SM_VL };
    const uint32_t skh = smem_u32(smb + SM_KH);
    const uint32_t skl = smem_u32(smb + SM_KL);
    const uint32_t svh = smem_u32(smb + SM_VH);
    const uint32_t svl = smem_u32(smb + SM_VL);

    const int tid  = threadIdx.x;
    const int wid  = tid >> 5;
    const int lane = tid & 31;
    const int g    = lane >> 2;
    const int tig  = lane & 3;
    const int lq   = lane >> 3;
    const int lr   = lane & 7;
    const int qtile = (int)gridDim.x - 1 - (int)blockIdx.x;
    const int bh    = blockIdx.y;

    const size_t qkbase = ((size_t)bh * T_ + (size_t)qtile * 128) * HD_;
    const size_t kvrow0 = (size_t)bh * T_ * HD_;
    const size_t vtbase = (size_t)bh * HD_ * T_;

    const uint32_t aRow = lr + (lq & 1) * 8;
    const uint32_t aCol = (lq >> 1) * 16;
    const uint32_t bRow = lr + (lq >> 1) * 8;
    const uint32_t bCol = (lq & 1) * 16;

    // ---- stage Q, extract A-fragments via ldmatrix, release smem ----
    {
        const __nv_bfloat16* qsrc[2] = { g_qh + qkbase, g_ql + qkbase };
#pragma unroll
        for (int p = 0; p < 8; p++) {
            const int c   = tid + p * 256;
            const int mat = c >> 10;
            const int rem = c & 1023;
            const int r   = rem >> 3;
            const int c8  = (rem & 7) * 8;
            *(uint4*)(Karr[mat] + r * KPIT + c8) =
                *(const uint4*)(qsrc[mat] + r * HD_ + c8);
        }
    }
    __syncthreads();

    uint32_t qfh[4][4], qfl[4][4];
#pragma unroll
    for (int kb = 0; kb < 4; kb++) {
        const uint32_t qo = (16 * wid + aRow) * (KPIT * 2) + kb * 32 + aCol;
        ldsm4(qfh[kb], skh + qo);
        ldsm4(qfl[kb], skl + qo);
    }

    float o[8][4];
#pragma unroll
    for (int nt = 0; nt < 8; nt++)
#pragma unroll
        for (int e = 0; e < 4; e++) o[nt][e] = 0.0f;
    float m0 = -INFINITY, m1 = -INFINITY, l0 = 0.0f, l1 = 0.0f;

    for (int kv = 0; kv <= qtile; kv++) {
        __syncthreads();
        {
            const __nv_bfloat16* ksrc[2] = { g_kh + kvrow0 + (size_t)kv * 128 * HD_,
                                             g_kl + kvrow0 + (size_t)kv * 128 * HD_ };
            const __nv_bfloat16* vsrc[2] = { g_vth + vtbase + (size_t)kv * 128,
                                             g_vtl + vtbase + (size_t)kv * 128 };
#pragma unroll
            for (int p = 0; p < 8; p++) {
                const int c   = tid + p * 256;
                const int mat = c >> 10;
                const int rem = c & 1023;
                const int r   = rem >> 3;
                const int c8  = (rem & 7) * 8;
                *(uint4*)(Karr[mat] + r * KPIT + c8) =
                    *(const uint4*)(ksrc[mat] + r * HD_ + c8);
            }
#pragma unroll
            for (int p = 0; p < 8; p++) {
                const int c   = tid + p * 256;
                const int mat = c >> 10;
                const int rem = c & 1023;
                const int d   = rem >> 4;
                const int c8  = (rem & 15) * 8;
                *(uint4*)(Varr[mat] + d * VPIT + c8) =
                    *(const uint4*)(vsrc[mat] + (size_t)d * T_ + c8);
            }
        }
        __syncthreads();

        // ---- S = Q K^T (split 3-mma) ----
        float cS[16][4];
#pragma unroll
        for (int j = 0; j < 16; j++)
#pragma unroll
            for (int e = 0; e < 4; e++) cS[j][e] = 0.0f;

#pragma unroll
        for (int kb = 0; kb < 4; kb++) {
#pragma unroll
            for (int jp = 0; jp < 8; jp++) {
                const uint32_t koff = (jp * 16 + bRow) * (KPIT * 2) + kb * 32 + bCol;
                uint32_t th[4], tl[4];
                ldsm4(th, skh + koff);
                mma_bf16(cS[2*jp],   qfh[kb], th);
                mma_bf16(cS[2*jp],   qfl[kb], th);
                mma_bf16(cS[2*jp+1], qfh[kb], th + 2);
                mma_bf16(cS[2*jp+1], qfl[kb], th + 2);
                ldsm4(tl, skl + koff);
                mma_bf16(cS[2*jp],   qfh[kb], tl);
                mma_bf16(cS[2*jp+1], qfh[kb], tl + 2);
            }
        }

        // ---- scale + causal mask ----
        const bool diag = (kv == qtile);
        const int row0 = 16 * wid + g;
#pragma unroll
        for (int j = 0; j < 16; j++) {
            const int col0 = j * 8 + 2 * tig;
            cS[j][0] *= 0.125f; cS[j][1] *= 0.125f;
            cS[j][2] *= 0.125f; cS[j][3] *= 0.125f;
            if (diag) {
                if (col0     > row0)     cS[j][0] = -1e30f;
                if (col0 + 1 > row0)     cS[j][1] = -1e30f;
                if (col0     > row0 + 8) cS[j][2] = -1e30f;
                if (col0 + 1 > row0 + 8) cS[j][3] = -1e30f;
            }
        }

        // ---- online softmax ----
        float mx0 = -INFINITY, mx1 = -INFINITY;
#pragma unroll
        for (int j = 0; j < 16; j++) {
            mx0 = fmaxf(mx0, fmaxf(cS[j][0], cS[j][1]));
            mx1 = fmaxf(mx1, fmaxf(cS[j][2], cS[j][3]));
        }
        mx0 = fmaxf(mx0, __shfl_xor_sync(0xffffffffu, mx0, 1));
        mx0 = fmaxf(mx0, __shfl_xor_sync(0xffffffffu, mx0, 2));
        mx1 = fmaxf(mx1, __shfl_xor_sync(0xffffffffu, mx1, 1));
        mx1 = fmaxf(mx1, __shfl_xor_sync(0xffffffffu, mx1, 2));

        const float nm0 = fmaxf(m0, mx0), nm1 = fmaxf(m1, mx1);
        const float al0 = __expf(m0 - nm0), al1 = __expf(m1 - nm1);
        m0 = nm0; m1 = nm1;

        float rs0 = 0.0f, rs1 = 0.0f;
#pragma unroll
        for (int j = 0; j < 16; j++) {
            cS[j][0] = __expf(cS[j][0] - m0);
            cS[j][1] = __expf(cS[j][1] - m0);
            cS[j][2] = __expf(cS[j][2] - m1);
            cS[j][3] = __expf(cS[j][3] - m1);
            rs0 += cS[j][0] + cS[j][1];
            rs1 += cS[j][2] + cS[j][3];
        }
        rs0 += __shfl_xor_sync(0xffffffffu, rs0, 1);
        rs0 += __shfl_xor_sync(0xffffffffu, rs0, 2);
        rs1 += __shfl_xor_sync(0xffffffffu, rs1, 1);
        rs1 += __shfl_xor_sync(0xffffffffu, rs1, 2);
        l0 = l0 * al0 + rs0;
        l1 = l1 * al1 + rs1;

#pragma unroll
        for (int nt = 0; nt < 8; nt++) {
            o[nt][0] *= al0; o[nt][1] *= al0;
            o[nt][2] *= al1; o[nt][3] *= al1;
        }

        // ---- PV ----
#pragma unroll
        for (int kb2 = 0; kb2 < 8; kb2++) {
            uint32_t aph[4], apl[4];
            split2(cS[2*kb2][0],   cS[2*kb2][1],   aph[0], apl[0]);
            split2(cS[2*kb2][2],   cS[2*kb2][3],   aph[1], apl[1]);
            split2(cS[2*kb2+1][0], cS[2*kb2+1][1], aph[2], apl[2]);
            split2(cS[2*kb2+1][2], cS[2*kb2+1][3], aph[3], apl[3]);
#pragma unroll
            for (int np = 0; np < 4; np++) {
                const uint32_t voff = (np * 16 + bRow) * (VPIT * 2) + kb2 * 32 + bCol;
                uint32_t th[4], tl[4];
                ldsm4(th, svh + voff);
                mma_bf16(o[2*np],   aph, th);
                mma_bf16(o[2*np],   apl, th);
                mma_bf16(o[2*np+1], aph, th + 2);
                mma_bf16(o[2*np+1], apl, th + 2);
                ldsm4(tl, svl + voff);
                mma_bf16(o[2*np],   aph, tl);
                mma_bf16(o[2*np+1], aph, tl + 2);
            }
        }
    }

    // ---- epilogue ----
    const int b = bh >> 4;
    const int h = bh & 15;
    const int t0 = qtile * 128 + 16 * wid + g;
    const float inv0 = 1.0f / l0, inv1 = 1.0f / l1;
#pragma unroll
    for (int nt = 0; nt < 8; nt++) {
        const int d = nt * 8 + 2 * tig;
        uint32_t ph, pl;
        split2(o[nt][0] * inv0, o[nt][1] * inv0, ph, pl);
        const size_t off0 = ((size_t)b * T_ + t0) * D_ + h * HD_ + d;
        *(uint32_t*)(g_atth + off0) = ph;
        *(uint32_t*)(g_attl + off0) = pl;
        split2(o[nt][2] * inv1, o[nt][3] * inv1, ph, pl);
        const size_t off1 = ((size_t)b * T_ + t0 + 8) * D_ + h * HD_ + d;
        *(uint32_t*)(g_atth + off1) = ph;
        *(uint32_t*)(g_attl + off1) = pl;
    }
}

// ---------------------------------------------------------------------------
extern "C" void kernel_launch(void* const* d_in, const int* in_sizes, int n_in,
                              void* d_out, int out_size)
{
    const float* x     = (const float*)d_in[0];
    // d_in[1] = mask (causal, static — ignored)
    const float* w_qkv = (const float*)d_in[2];
    const float* w_out = (const float*)d_in[3];
    float* out = (float*)d_out;

    cudaFuncSetAttribute(bgemm<0>, cudaFuncAttributeMaxDynamicSharedMemorySize, BGEMM_SMEM);
    cudaFuncSetAttribute(bgemm<1>, cudaFuncAttributeMaxDynamicSharedMemorySize, BGEMM_SMEM);
    cudaFuncSetAttribute(flash_tc, cudaFuncAttributeMaxDynamicSharedMemorySize, FLASH_SMEM);

    __nv_bfloat16 *xh, *xl, *wqh, *wql, *woh, *wol, *ath, *atl;
    cudaGetSymbolAddress((void**)&xh,  g_xh);     cudaGetSymbolAddress((void**)&xl,  g_xl);
    cudaGetSymbolAddress((void**)&wqh, g_wqkvTh); cudaGetSymbolAddress((void**)&wql, g_wqkvTl);
    cudaGetSymbolAddress((void**)&woh, g_woutTh); cudaGetSymbolAddress((void**)&wol, g_woutTl);
    cudaGetSymbolAddress((void**)&ath, g_atth);   cudaGetSymbolAddress((void**)&atl, g_attl);

    // 0) split x; split+transpose weights
    split4_kernel<<<(M_*D_/4 + 255)/256, 256>>>((const float4*)x,
        (__nv_bfloat162*)xh, (__nv_bfloat162*)xl, M_*D_/4);
    splitT_kernel<<<dim3(NQKV_/32, D_/32), dim3(32, 8)>>>(w_qkv, wqh, wql, D_, NQKV_);
    splitT_kernel<<<dim3(D_/32,  D_/32), dim3(32, 8)>>>(w_out, woh, wol, D_, D_);

    // 1) qkv = x @ w_qkv (tensor)
    bgemm<0><<<dim3(NQKV_/128, M_/128), 256, BGEMM_SMEM>>>(xh, xl, wqh, wql,
                                                           nullptr, NQKV_, K_);
    // 2) RoPE -> split bf16 q/k (paired stores);  V -> transpose+split (paired)
    rope_kernel<<<(B_ * H_ * T_ * 16) / 256, 256>>>();
    vsplitT_kernel<<<dim3(T_/32, HD_/32, B_*H_), dim3(32, 8)>>>();

    // 3) tensor-core causal flash attention (exact R10)
    flash_tc<<<dim3(T_ / 128, B_ * H_), 256, FLASH_SMEM>>>();

    // 4) out = att @ w_out (tensor)
    bgemm<1><<<dim3(D_/128, M_/128), 256, BGEMM_SMEM>>>(ath, atl, woh, wol,
                                                        out, D_, K_);
}

// round 15
// speedup vs baseline: 1.0683x; 1.0048x over previous
#include <cuda_runtime.h>
#include <cuda_bf16.h>
#include <math.h>
#include <stdint.h>

// Problem constants
#define B_   2
#define H_   16
#define T_   2048
#define D_   1024
#define HD_  64
#define M_   (B_*T_)      // 4096 rows
#define NQKV_ (3*D_)      // 3072
#define K_   1024

// bf16 split operands (device globals: allocation-free rule)
__device__ __align__(16) __nv_bfloat16 g_xh[M_*D_],    g_xl[M_*D_];
__device__ __align__(16) __nv_bfloat16 g_wqkvTh[NQKV_*D_], g_wqkvTl[NQKV_*D_];
__device__ __align__(16) __nv_bfloat16 g_woutTh[D_*D_],   g_woutTl[D_*D_];
__device__ __align__(16) __nv_bfloat16 g_atth[M_*D_],  g_attl[M_*D_];
__device__ __align__(16) __nv_bfloat16 g_qh[B_*H_*T_*HD_], g_ql[B_*H_*T_*HD_];  // [bh][t][d]
__device__ __align__(16) __nv_bfloat16 g_kh[B_*H_*T_*HD_], g_kl[B_*H_*T_*HD_];  // [bh][t][d]
__device__ __align__(16) __nv_bfloat16 g_vth[B_*H_*T_*HD_], g_vtl[B_*H_*T_*HD_]; // [bh][d][t]

__device__ __forceinline__ uint32_t smem_u32(const void* p) {
    uint32_t a;
    asm("{ .reg .u64 t; cvta.to.shared.u64 t, %1; cvt.u32.u64 %0, t; }" : "=r"(a) : "l"(p));
    return a;
}
__device__ __forceinline__ void cp_async16(uint32_t dst, const void* src) {
    asm volatile("cp.async.cg.shared.global [%0], [%1], 16;" :: "r"(dst), "l"(src));
}
__device__ __forceinline__ void cp_commit() { asm volatile("cp.async.commit_group;" ::: "memory"); }
__device__ __forceinline__ void cp_wait0()  { asm volatile("cp.async.wait_group 0;" ::: "memory"); }
__device__ __forceinline__ void ldsm4(uint32_t r[4], uint32_t addr) {
    asm volatile("ldmatrix.sync.aligned.m8n8.x4.shared.b16 {%0,%1,%2,%3}, [%4];"
        : "=r"(r[0]), "=r"(r[1]), "=r"(r[2]), "=r"(r[3]) : "r"(addr));
}
__device__ __forceinline__ void mma_bf16(float c[4], const uint32_t a[4], const uint32_t b[2]) {
    asm volatile(
        "mma.sync.aligned.m16n8k16.row.col.f32.bf16.bf16.f32 "
        "{%0,%1,%2,%3}, {%4,%5,%6,%7}, {%8,%9}, {%0,%1,%2,%3};"
        : "+f"(c[0]), "+f"(c[1]), "+f"(c[2]), "+f"(c[3])
        : "r"(a[0]), "r"(a[1]), "r"(a[2]), "r"(a[3]), "r"(b[0]), "r"(b[1]));
}
__device__ __forceinline__ void split1(float v, __nv_bfloat16& h, __nv_bfloat16& l) {
    h = __float2bfloat16(v);
    l = __float2bfloat16(v - __bfloat162float(h));
}
__device__ __forceinline__ void split2(float x, float y, uint32_t& h, uint32_t& l) {
    __nv_bfloat16 hx, lx, hy, ly;
    split1(x, hx, lx); split1(y, hy, ly);
    __nv_bfloat162 hv(hx, hy), lv(lx, ly);
    h = *(uint32_t*)&hv; l = *(uint32_t*)&lv;
}

// ---------------------------------------------------------------------------
// Feeders: split x, split+transpose weights
// ---------------------------------------------------------------------------
__global__ void split4_kernel(const float4* __restrict__ src,
                              __nv_bfloat162* __restrict__ h,
                              __nv_bfloat162* __restrict__ l, int n4)
{
    const int i = blockIdx.x * blockDim.x + threadIdx.x;
    if (i >= n4) return;
    const float4 v = src[i];
    __nv_bfloat16 hx, lx, hy, ly, hz, lz, hw, lw;
    split1(v.x, hx, lx); split1(v.y, hy, ly);
    split1(v.z, hz, lz); split1(v.w, hw, lw);
    h[2*i]   = __nv_bfloat162(hx, hy);
    h[2*i+1] = __nv_bfloat162(hz, hw);
    l[2*i]   = __nv_bfloat162(lx, ly);
    l[2*i+1] = __nv_bfloat162(lz, lw);
}

__global__ void splitT_kernel(const float* __restrict__ src,
                              __nv_bfloat16* __restrict__ hT,
                              __nv_bfloat16* __restrict__ lT, int R, int C)
{
    __shared__ float tile[32][33];
    const int bx = blockIdx.x * 32, by = blockIdx.y * 32;
    const int tx = threadIdx.x, ty = threadIdx.y;
#pragma unroll
    for (int i = 0; i < 32; i += 8)
        tile[ty + i][tx] = src[(size_t)(by + ty + i) * C + bx + tx];
    __syncthreads();
#pragma unroll
    for (int i = 0; i < 32; i += 8) {
        const float v = tile[tx][ty + i];
        __nv_bfloat16 h, l;
        split1(v, h, l);
        const size_t o = (size_t)(bx + ty + i) * R + by + tx;
        hT[o] = h; lT[o] = l;
    }
}

// ---------------------------------------------------------------------------
// bf16 split-GEMM with ldmatrix fragment loading.
// MODE 0: fused epilogue — stage fp32 result in smem (pitch 132, float2-safe),
//   part q/k: RoPE + split -> g_qh/l, g_kh/l; part v: transpose+split -> g_vth/l
// MODE 1: plain fp32 store to Cout.
// ---------------------------------------------------------------------------
#define PB    40
#define MATB  (128 * PB * 2)
#define BUFB  (4 * MATB)
#define BGEMM_SMEM (2 * BUFB)     // 81920 B; epilogue reuses as 128x132 fp32 (67584 B)
#define CPIT  132                 // EVEN pitch: float2 stores stay 8B-aligned

template<int MODE>
__global__ __launch_bounds__(256, 2)
void bgemm(const __nv_bfloat16* __restrict__ Ah, const __nv_bfloat16* __restrict__ Al,
           const __nv_bfloat16* __restrict__ Bh, const __nv_bfloat16* __restrict__ Bl,
           float* __restrict__ Cout, int N, int K)
{
    extern __shared__ char smc[];
    const uint32_t sb = smem_u32(smc);

    const int tid  = threadIdx.x;
    const int wid  = tid >> 5;
    const int lane = tid & 31;
    const int g    = lane >> 2;
    const int tig  = lane & 3;
    const int lq   = lane >> 3;
    const int lr   = lane & 7;
    const int warp_m = wid >> 2;
    const int warp_n = wid & 3;
    const int bm = blockIdx.y;
    const int bn = blockIdx.x;

    const char* gsrc[4] = {
        (const char*)(Ah + (size_t)bm * 128 * K),
        (const char*)(Al + (size_t)bm * 128 * K),
        (const char*)(Bh + (size_t)bn * 128 * K),
        (const char*)(Bl + (size_t)bn * 128 * K)
    };
    const size_t grs = (size_t)K * 2;

    float acc[4][4][4];
#pragma unroll
    for (int i = 0; i < 4; i++)
#pragma unroll
        for (int j = 0; j < 4; j++)
#pragma unroll
            for (int e = 0; e < 4; e++) acc[i][j][e] = 0.0f;

    const int NT = K / 32;

#pragma unroll
    for (int p = 0; p < 8; p++) {
        const int c   = tid + p * 256;
        const int mat = c >> 9;
        const int r   = (c >> 2) & 127;
        const int q   = (c & 3) * 16;
        cp_async16(sb + mat * MATB + r * (PB * 2) + q,
                   gsrc[mat] + (size_t)r * grs + q);
    }
    cp_commit();
    cp_wait0();
    __syncthreads();

    const uint32_t aRow = lr + (lq & 1) * 8;
    const uint32_t aCol = (lq >> 1) * 16;
    const uint32_t bRow = lr + (lq >> 1) * 8;
    const uint32_t bCol = (lq & 1) * 16;

    for (int t = 0; t < NT; t++) {
        const int buf = t & 1;

        if (t + 1 < NT) {
            const uint32_t db = sb + (buf ^ 1) * BUFB;
            const size_t kb = (size_t)(t + 1) * 64;
#pragma unroll
            for (int p = 0; p < 8; p++) {
                const int c   = tid + p * 256;
                const int mat = c >> 9;
                const int r   = (c >> 2) & 127;
                const int q   = (c & 3) * 16;
                cp_async16(db + mat * MATB + r * (PB * 2) + q,
                           gsrc[mat] + (size_t)r * grs + kb + q);
            }
            cp_commit();
        }

        const uint32_t base = sb + buf * BUFB;
#pragma unroll
        for (int ks = 0; ks < 2; ks++) {
            const uint32_t ko = ks * 32;

            uint32_t ah[4][4], al[4][4], bh[4][2], bl[4][2];
#pragma unroll
            for (int i = 0; i < 4; i++) {
                const uint32_t ao = (warp_m * 64 + i * 16 + aRow) * (PB * 2) + ko + aCol;
                ldsm4(ah[i], base + ao);
                ldsm4(al[i], base + MATB + ao);
            }
#pragma unroll
            for (int jp = 0; jp < 2; jp++) {
                const uint32_t bo = (warp_n * 32 + jp * 16 + bRow) * (PB * 2) + ko + bCol;
                uint32_t th[4], tl[4];
                ldsm4(th, base + 2 * MATB + bo);
                bh[2*jp][0] = th[0]; bh[2*jp][1] = th[1];
                bh[2*jp+1][0] = th[2]; bh[2*jp+1][1] = th[3];
                ldsm4(tl, base + 3 * MATB + bo);
                bl[2*jp][0] = tl[0]; bl[2*jp][1] = tl[1];
                bl[2*jp+1][0] = tl[2]; bl[2*jp+1][1] = tl[3];
            }

#pragma unroll
            for (int i = 0; i < 4; i++)
#pragma unroll
                for (int j = 0; j < 4; j++)
                    mma_bf16(acc[i][j], ah[i], bh[j]);
#pragma unroll
            for (int i = 0; i < 4; i++)
#pragma unroll
                for (int j = 0; j < 4; j++)
                    mma_bf16(acc[i][j], al[i], bh[j]);
#pragma unroll
            for (int i = 0; i < 4; i++)
#pragma unroll
                for (int j = 0; j < 4; j++)
                    mma_bf16(acc[i][j], ah[i], bl[j]);
        }

        if (t + 1 < NT) cp_wait0();
        __syncthreads();
    }

    if (MODE == 1) {
        // plain fp32 store
#pragma unroll
        for (int i = 0; i < 4; i++) {
            const int r0 = bm * 128 + warp_m * 64 + i * 16 + g;
#pragma unroll
            for (int j = 0; j < 4; j++) {
                const int c0 = bn * 128 + warp_n * 32 + j * 8 + tig * 2;
#pragma unroll
                for (int half = 0; half < 2; half++) {
                    const int r = r0 + half * 8;
                    *(float2*)(Cout + (size_t)r * N + c0) =
                        make_float2(acc[i][j][half * 2], acc[i][j][half * 2 + 1]);
                }
            }
        }
        return;
    }

    // ---- MODE 0 fused epilogue: stage fp32 tile into (now free) smem ----
    __syncthreads();   // all warps done reading operand smem
    float* Cs = (float*)smc;
#pragma unroll
    for (int i = 0; i < 4; i++) {
        const int rl0 = warp_m * 64 + i * 16 + g;
#pragma unroll
        for (int j = 0; j < 4; j++) {
            const int cl = warp_n * 32 + j * 8 + tig * 2;
#pragma unroll
            for (int half = 0; half < 2; half++) {
                const int rl = rl0 + half * 8;
                *(float2*)&Cs[rl * CPIT + cl] =
                    make_float2(acc[i][j][half * 2], acc[i][j][half * 2 + 1]);
            }
        }
    }
    __syncthreads();

    const int part  = bn >> 3;                 // 0:q 1:k 2:v
    const int b     = (bm * 128) >> 11;        // batch
    const int trow0 = (bm * 128) & (T_ - 1);   // first t of tile
    const int h0    = (bn & 7) * 2;            // first head covered

    if (part < 2) {
        __nv_bfloat16* dh = (part == 0) ? g_qh : g_kh;
        __nv_bfloat16* dl = (part == 0) ? g_ql : g_kl;
        // 128 rows x 2 heads x 16 even-j = 4096 items
        for (int it = tid; it < 4096; it += 256) {
            const int r  = it >> 5;
            const int hh = (it >> 4) & 1;
            const int j  = (it & 15) * 2;      // even d in [0,32)
            const int t  = trow0 + r;
            const float* row = &Cs[r * CPIT + hh * 64];
            const float a0 = row[j],      a1 = row[j + 1];
            const float b0 = row[j + 32], b1 = row[j + 33];
            const float f0 = exp2f(-(float)j       * (13.287712379549449f / 32.0f));
            const float f1 = exp2f(-(float)(j + 1) * (13.287712379549449f / 32.0f));
            float s0, c0, s1, c1;
            sincosf((float)t * f0, &s0, &c0);
            sincosf((float)t * f1, &s1, &c1);
            const float o0 = a0 * c0 - b0 * s0, o1 = a1 * c1 - b1 * s1;  // d, d+1
            const float p0 = b0 * c0 + a0 * s0, p1 = b1 * c1 + a1 * s1;  // d+32, d+33
            const size_t basep = ((size_t)(b * H_ + h0 + hh) * T_ + t) * HD_;
            uint32_t ph, pl;
            split2(o0, o1, ph, pl);
            *(uint32_t*)(dh + basep + j) = ph;      *(uint32_t*)(dl + basep + j) = pl;
            split2(p0, p1, ph, pl);
            *(uint32_t*)(dh + basep + j + 32) = ph; *(uint32_t*)(dl + basep + j + 32) = pl;
        }
    } else {
        // v: transpose + split -> g_vth/l [bh][d][t]; 128 idx x 64 t-pairs = 8192 items
        for (int it = tid; it < 8192; it += 256) {
            const int d  = it >> 6;            // 0..127 (2 heads x 64)
            const int tp = it & 63;            // t-pair
            const float v0 = Cs[(2 * tp)     * CPIT + d];
            const float v1 = Cs[(2 * tp + 1) * CPIT + d];
            const int hh = d >> 6, dd = d & 63;
            const size_t o = ((size_t)(b * H_ + h0 + hh) * HD_ + dd) * T_ + trow0 + 2 * tp;
            uint32_t ph, pl;
            split2(v0, v1, ph, pl);
            *(uint32_t*)(g_vth + o) = ph;
            *(uint32_t*)(g_vtl + o) = pl;
        }
    }
}

// ---------------------------------------------------------------------------
// Tensor-core flash attention — EXACT R10 structure (single buffer, 2 CTA/SM).
// ---------------------------------------------------------------------------
#define KPIT 72
#define VPIT 136
#define SM_KH 0
#define SM_KL (128 * KPIT)
#define SM_VH (2 * 128 * KPIT)
#define SM_VL (2 * 128 * KPIT + 64 * VPIT)
#define FLASH_SMEM ((2 * 128 * KPIT + 2 * 64 * VPIT) * 2)

__global__ __launch_bounds__(256, 1)
void flash_tc()
{
    extern __shared__ __nv_bfloat16 smb[];
    __nv_bfloat16* Karr[2] = { smb + SM_KH, smb + SM_KL };
    __nv_bfloat16* Varr[2] = { smb + SM_VH, smb + SM_VL };
    const uint32_t skh = smem_u32(smb + SM_KH);
    const uint32_t skl = smem_u32(smb + SM_KL);
    const uint32_t svh = smem_u32(smb + SM_VH);
    const uint32_t svl = smem_u32(smb + SM_VL);

    const int tid  = threadIdx.x;
    const int wid  = tid >> 5;
    const int lane = tid & 31;
    const int g    = lane >> 2;
    const int tig  = lane & 3;
    const int lq   = lane >> 3;
    const int lr   = lane & 7;
    const int qtile = (int)gridDim.x - 1 - (int)blockIdx.x;
    const int bh    = blockIdx.y;

    const size_t qkbase = ((size_t)bh * T_ + (size_t)qtile * 128) * HD_;
    const size_t kvrow0 = (size_t)bh * T_ * HD_;
    const size_t vtbase = (size_t)bh * HD_ * T_;

    const uint32_t aRow = lr + (lq & 1) * 8;
    const uint32_t aCol = (lq >> 1) * 16;
    const uint32_t bRow = lr + (lq >> 1) * 8;
    const uint32_t bCol = (lq & 1) * 16;

    // ---- stage Q, extract A-fragments via ldmatrix, release smem ----
    {
        const __nv_bfloat16* qsrc[2] = { g_qh + qkbase, g_ql + qkbase };
#pragma unroll
        for (int p = 0; p < 8; p++) {
            const int c   = tid + p * 256;
            const int mat = c >> 10;
            const int rem = c & 1023;
            const int r   = rem >> 3;
            const int c8  = (rem & 7) * 8;
            *(uint4*)(Karr[mat] + r * KPIT + c8) =
                *(const uint4*)(qsrc[mat] + r * HD_ + c8);
        }
    }
    __syncthreads();

    uint32_t qfh[4][4], qfl[4][4];
#pragma unroll
    for (int kb = 0; kb < 4; kb++) {
        const uint32_t qo = (16 * wid + aRow) * (KPIT * 2) + kb * 32 + aCol;
        ldsm4(qfh[kb], skh + qo);
        ldsm4(qfl[kb], skl + qo);
    }

    float o[8][4];
#pragma unroll
    for (int nt = 0; nt < 8; nt++)
#pragma unroll
        for (int e = 0; e < 4; e++) o[nt][e] = 0.0f;
    float m0 = -INFINITY, m1 = -INFINITY, l0 = 0.0f, l1 = 0.0f;

    for (int kv = 0; kv <= qtile; kv++) {
        __syncthreads();
        {
            const __nv_bfloat16* ksrc[2] = { g_kh + kvrow0 + (size_t)kv * 128 * HD_,
                                             g_kl + kvrow0 + (size_t)kv * 128 * HD_ };
            const __nv_bfloat16* vsrc[2] = { g_vth + vtbase + (size_t)kv * 128,
                                             g_vtl + vtbase + (size_t)kv * 128 };
#pragma unroll
            for (int p = 0; p < 8; p++) {
                const int c   = tid + p * 256;
                const int mat = c >> 10;
                const int rem = c & 1023;
                const int r   = rem >> 3;
                const int c8  = (rem & 7) * 8;
                *(uint4*)(Karr[mat] + r * KPIT + c8) =
                    *(const uint4*)(ksrc[mat] + r * HD_ + c8);
            }
#pragma unroll
            for (int p = 0; p < 8; p++) {
                const int c   = tid + p * 256;
                const int mat = c >> 10;
                const int rem = c & 1023;
                const int d   = rem >> 4;
                const int c8  = (rem & 15) * 8;
                *(uint4*)(Varr[mat] + d * VPIT + c8) =
                    *(const uint4*)(vsrc[mat] + (size_t)d * T_ + c8);
            }
        }
        __syncthreads();

        // ---- S = Q K^T (split 3-mma) ----
        float cS[16][4];
#pragma unroll
        for (int j = 0; j < 16; j++)
#pragma unroll
            for (int e = 0; e < 4; e++) cS[j][e] = 0.0f;

#pragma unroll
        for (int kb = 0; kb < 4; kb++) {
#pragma unroll
            for (int jp = 0; jp < 8; jp++) {
                const uint32_t koff = (jp * 16 + bRow) * (KPIT * 2) + kb * 32 + bCol;
                uint32_t th[4], tl[4];
                ldsm4(th, skh + koff);
                mma_bf16(cS[2*jp],   qfh[kb], th);
                mma_bf16(cS[2*jp],   qfl[kb], th);
                mma_bf16(cS[2*jp+1], qfh[kb], th + 2);
                mma_bf16(cS[2*jp+1], qfl[kb], th + 2);
                ldsm4(tl, skl + koff);
                mma_bf16(cS[2*jp],   qfh[kb], tl);
                mma_bf16(cS[2*jp+1], qfh[kb], tl + 2);
            }
        }

        // ---- scale + causal mask ----
        const bool diag = (kv == qtile);
        const int row0 = 16 * wid + g;
#pragma unroll
        for (int j = 0; j < 16; j++) {
            const int col0 = j * 8 + 2 * tig;
            cS[j][0] *= 0.125f; cS[j][1] *= 0.125f;
            cS[j][2] *= 0.125f; cS[j][3] *= 0.125f;
            if (diag) {
                if (col0     > row0)     cS[j][0] = -1e30f;
                if (col0 + 1 > row0)     cS[j][1] = -1e30f;
                if (col0     > row0 + 8) cS[j][2] = -1e30f;
                if (col0 + 1 > row0 + 8) cS[j][3] = -1e30f;
            }
        }

        // ---- online softmax ----
        float mx0 = -INFINITY, mx1 = -INFINITY;
#pragma unroll
        for (int j = 0; j < 16; j++) {
            mx0 = fmaxf(mx0, fmaxf(cS[j][0], cS[j][1]));
            mx1 = fmaxf(mx1, fmaxf(cS[j][2], cS[j][3]));
        }
        mx0 = fmaxf(mx0, __shfl_xor_sync(0xffffffffu, mx0, 1));
        mx0 = fmaxf(mx0, __shfl_xor_sync(0xffffffffu, mx0, 2));
        mx1 = fmaxf(mx1, __shfl_xor_sync(0xffffffffu, mx1, 1));
        mx1 = fmaxf(mx1, __shfl_xor_sync(0xffffffffu, mx1, 2));

        const float nm0 = fmaxf(m0, mx0), nm1 = fmaxf(m1, mx1);
        const float al0 = __expf(m0 - nm0), al1 = __expf(m1 - nm1);
        m0 = nm0; m1 = nm1;

        float rs0 = 0.0f, rs1 = 0.0f;
#pragma unroll
        for (int j = 0; j < 16; j++) {
            cS[j][0] = __expf(cS[j][0] - m0);
            cS[j][1] = __expf(cS[j][1] - m0);
            cS[j][2] = __expf(cS[j][2] - m1);
            cS[j][3] = __expf(cS[j][3] - m1);
            rs0 += cS[j][0] + cS[j][1];
            rs1 += cS[j][2] + cS[j][3];
        }
        rs0 += __shfl_xor_sync(0xffffffffu, rs0, 1);
        rs0 += __shfl_xor_sync(0xffffffffu, rs0, 2);
        rs1 += __shfl_xor_sync(0xffffffffu, rs1, 1);
        rs1 += __shfl_xor_sync(0xffffffffu, rs1, 2);
        l0 = l0 * al0 + rs0;
        l1 = l1 * al1 + rs1;

#pragma unroll
        for (int nt = 0; nt < 8; nt++) {
            o[nt][0] *= al0; o[nt][1] *= al0;
            o[nt][2] *= al1; o[nt][3] *= al1;
        }

        // ---- PV ----
#pragma unroll
        for (int kb2 = 0; kb2 < 8; kb2++) {
            uint32_t aph[4], apl[4];
            split2(cS[2*kb2][0],   cS[2*kb2][1],   aph[0], apl[0]);
            split2(cS[2*kb2][2],   cS[2*kb2][3],   aph[1], apl[1]);
            split2(cS[2*kb2+1][0], cS[2*kb2+1][1], aph[2], apl[2]);
            split2(cS[2*kb2+1][2], cS[2*kb2+1][3], aph[3], apl[3]);
#pragma unroll
            for (int np = 0; np < 4; np++) {
                const uint32_t voff = (np * 16 + bRow) * (VPIT * 2) + kb2 * 32 + bCol;
                uint32_t th[4], tl[4];
                ldsm4(th, svh + voff);
                mma_bf16(o[2*np],   aph, th);
                mma_bf16(o[2*np],   apl, th);
                mma_bf16(o[2*np+1], aph, th + 2);
                mma_bf16(o[2*np+1], apl, th + 2);
                ldsm4(tl, svl + voff);
                mma_bf16(o[2*np],   aph, tl);
                mma_bf16(o[2*np+1], aph, tl + 2);
            }
        }
    }

    // ---- epilogue ----
    const int b = bh >> 4;
    const int h = bh & 15;
    const int t0 = qtile * 128 + 16 * wid + g;
    const float inv0 = 1.0f / l0, inv1 = 1.0f / l1;
#pragma unroll
    for (int nt = 0; nt < 8; nt++) {
        const int d = nt * 8 + 2 * tig;
        uint32_t ph, pl;
        split2(o[nt][0] * inv0, o[nt][1] * inv0, ph, pl);
        const size_t off0 = ((size_t)b * T_ + t0) * D_ + h * HD_ + d;
        *(uint32_t*)(g_atth + off0) = ph;
        *(uint32_t*)(g_attl + off0) = pl;
        split2(o[nt][2] * inv1, o[nt][3] * inv1, ph, pl);
        const size_t off1 = ((size_t)b * T_ + t0 + 8) * D_ + h * HD_ + d;
        *(uint32_t*)(g_atth + off1) = ph;
        *(uint32_t*)(g_attl + off1) = pl;
    }
}

// ---------------------------------------------------------------------------
extern "C" void kernel_launch(void* const* d_in, const int* in_sizes, int n_in,
                              void* d_out, int out_size)
{
    const float* x     = (const float*)d_in[0];
    // d_in[1] = mask (causal, static — ignored)
    const float* w_qkv = (const float*)d_in[2];
    const float* w_out = (const float*)d_in[3];
    float* out = (float*)d_out;

    cudaFuncSetAttribute(bgemm<0>, cudaFuncAttributeMaxDynamicSharedMemorySize, BGEMM_SMEM);
    cudaFuncSetAttribute(bgemm<1>, cudaFuncAttributeMaxDynamicSharedMemorySize, BGEMM_SMEM);
    cudaFuncSetAttribute(flash_tc, cudaFuncAttributeMaxDynamicSharedMemorySize, FLASH_SMEM);

    __nv_bfloat16 *xh, *xl, *wqh, *wql, *woh, *wol, *ath, *atl;
    cudaGetSymbolAddress((void**)&xh,  g_xh);     cudaGetSymbolAddress((void**)&xl,  g_xl);
    cudaGetSymbolAddress((void**)&wqh, g_wqkvTh); cudaGetSymbolAddress((void**)&wql, g_wqkvTl);
    cudaGetSymbolAddress((void**)&woh, g_woutTh); cudaGetSymbolAddress((void**)&wol, g_woutTl);
    cudaGetSymbolAddress((void**)&ath, g_atth);   cudaGetSymbolAddress((void**)&atl, g_attl);

    // 0) split x; split+transpose weights
    split4_kernel<<<(M_*D_/4 + 255)/256, 256>>>((const float4*)x,
        (__nv_bfloat162*)xh, (__nv_bfloat162*)xl, M_*D_/4);
    splitT_kernel<<<dim3(NQKV_/32, D_/32), dim3(32, 8)>>>(w_qkv, wqh, wql, D_, NQKV_);
    splitT_kernel<<<dim3(D_/32,  D_/32), dim3(32, 8)>>>(w_out, woh, wol, D_, D_);

    // 1) qkv = x @ w_qkv (tensor) with fused RoPE/split/transpose epilogue
    bgemm<0><<<dim3(NQKV_/128, M_/128), 256, BGEMM_SMEM>>>(xh, xl, wqh, wql,
                                                           nullptr, NQKV_, K_);

    // 2) tensor-core causal flash attention
    flash_tc<<<dim3(T_ / 128, B_ * H_), 256, FLASH_SMEM>>>();

    // 3) out = att @ w_out (tensor)
    bgemm<1><<<dim3(D_/128, M_/128), 256, BGEMM_SMEM>>>(ath, atl, woh, wol,
                                                        out, D_, K_);
}

// round 16
// speedup vs baseline: 1.0706x; 1.0022x over previous
#include <cuda_runtime.h>
#include <cuda_bf16.h>
#include <math.h>
#include <stdint.h>

// Problem constants
#define B_   2
#define H_   16
#define T_   2048
#define D_   1024
#define HD_  64
#define M_   (B_*T_)      // 4096 rows
#define NQKV_ (3*D_)      // 3072
#define K_   1024

// bf16 split operands (device globals: allocation-free rule)
__device__ __align__(16) __nv_bfloat16 g_xh[M_*D_],    g_xl[M_*D_];
__device__ __align__(16) __nv_bfloat16 g_wqkvTh[NQKV_*D_], g_wqkvTl[NQKV_*D_];
__device__ __align__(16) __nv_bfloat16 g_woutTh[D_*D_],   g_woutTl[D_*D_];
__device__ __align__(16) __nv_bfloat16 g_atth[M_*D_],  g_attl[M_*D_];
__device__ __align__(16) __nv_bfloat16 g_qh[B_*H_*T_*HD_], g_ql[B_*H_*T_*HD_];  // [bh][t][d]
__device__ __align__(16) __nv_bfloat16 g_kh[B_*H_*T_*HD_], g_kl[B_*H_*T_*HD_];  // [bh][t][d]
__device__ __align__(16) __nv_bfloat16 g_vth[B_*H_*T_*HD_], g_vtl[B_*H_*T_*HD_]; // [bh][d][t]
// RoPE sin/cos table: [t][j], j in [0,32)
__device__ __align__(16) float g_rsin[T_*32], g_rcos[T_*32];

__device__ __forceinline__ uint32_t smem_u32(const void* p) {
    uint32_t a;
    asm("{ .reg .u64 t; cvta.to.shared.u64 t, %1; cvt.u32.u64 %0, t; }" : "=r"(a) : "l"(p));
    return a;
}
__device__ __forceinline__ void cp_async16(uint32_t dst, const void* src) {
    asm volatile("cp.async.cg.shared.global [%0], [%1], 16;" :: "r"(dst), "l"(src));
}
__device__ __forceinline__ void cp_commit() { asm volatile("cp.async.commit_group;" ::: "memory"); }
__device__ __forceinline__ void cp_wait0()  { asm volatile("cp.async.wait_group 0;" ::: "memory"); }
__device__ __forceinline__ void ldsm4(uint32_t r[4], uint32_t addr) {
    asm volatile("ldmatrix.sync.aligned.m8n8.x4.shared.b16 {%0,%1,%2,%3}, [%4];"
        : "=r"(r[0]), "=r"(r[1]), "=r"(r[2]), "=r"(r[3]) : "r"(addr));
}
__device__ __forceinline__ void mma_bf16(float c[4], const uint32_t a[4], const uint32_t b[2]) {
    asm volatile(
        "mma.sync.aligned.m16n8k16.row.col.f32.bf16.bf16.f32 "
        "{%0,%1,%2,%3}, {%4,%5,%6,%7}, {%8,%9}, {%0,%1,%2,%3};"
        : "+f"(c[0]), "+f"(c[1]), "+f"(c[2]), "+f"(c[3])
        : "r"(a[0]), "r"(a[1]), "r"(a[2]), "r"(a[3]), "r"(b[0]), "r"(b[1]));
}
__device__ __forceinline__ void split1(float v, __nv_bfloat16& h, __nv_bfloat16& l) {
    h = __float2bfloat16(v);
    l = __float2bfloat16(v - __bfloat162float(h));
}
__device__ __forceinline__ void split2(float x, float y, uint32_t& h, uint32_t& l) {
    __nv_bfloat16 hx, lx, hy, ly;
    split1(x, hx, lx); split1(y, hy, ly);
    __nv_bfloat162 hv(hx, hy), lv(lx, ly);
    h = *(uint32_t*)&hv; l = *(uint32_t*)&lv;
}

// ---------------------------------------------------------------------------
// Feeders: split x, split+transpose weights, RoPE table
// ---------------------------------------------------------------------------
__global__ void rope_table_kernel()
{
    const int idx = blockIdx.x * blockDim.x + threadIdx.x;   // T*32 threads
    const int j = idx & 31;
    const int t = idx >> 5;
    const float f = exp2f(-(float)j * (13.287712379549449f / 32.0f));
    float s, c;
    sincosf((float)t * f, &s, &c);
    g_rsin[idx] = s;
    g_rcos[idx] = c;
}

__global__ void split4_kernel(const float4* __restrict__ src,
                              __nv_bfloat162* __restrict__ h,
                              __nv_bfloat162* __restrict__ l, int n4)
{
    const int i = blockIdx.x * blockDim.x + threadIdx.x;
    if (i >= n4) return;
    const float4 v = src[i];
    __nv_bfloat16 hx, lx, hy, ly, hz, lz, hw, lw;
    split1(v.x, hx, lx); split1(v.y, hy, ly);
    split1(v.z, hz, lz); split1(v.w, hw, lw);
    h[2*i]   = __nv_bfloat162(hx, hy);
    h[2*i+1] = __nv_bfloat162(hz, hw);
    l[2*i]   = __nv_bfloat162(lx, ly);
    l[2*i+1] = __nv_bfloat162(lz, lw);
}

__global__ void splitT_kernel(const float* __restrict__ src,
                              __nv_bfloat16* __restrict__ hT,
                              __nv_bfloat16* __restrict__ lT, int R, int C)
{
    __shared__ float tile[32][33];
    const int bx = blockIdx.x * 32, by = blockIdx.y * 32;
    const int tx = threadIdx.x, ty = threadIdx.y;
#pragma unroll
    for (int i = 0; i < 32; i += 8)
        tile[ty + i][tx] = src[(size_t)(by + ty + i) * C + bx + tx];
    __syncthreads();
#pragma unroll
    for (int i = 0; i < 32; i += 8) {
        const float v = tile[tx][ty + i];
        __nv_bfloat16 h, l;
        split1(v, h, l);
        const size_t o = (size_t)(bx + ty + i) * R + by + tx;
        hT[o] = h; lT[o] = l;
    }
}

// ---------------------------------------------------------------------------
// bf16 split-GEMM with ldmatrix fragment loading.
// MODE 0: fused epilogue (table-driven RoPE + split; V transpose + split)
// MODE 1: plain fp32 store to Cout.
// ---------------------------------------------------------------------------
#define PB    40
#define MATB  (128 * PB * 2)
#define BUFB  (4 * MATB)
#define BGEMM_SMEM (2 * BUFB)     // 81920 B; epilogue reuses as 128x132 fp32
#define CPIT  132                 // EVEN pitch: float2 stores stay 8B-aligned

template<int MODE>
__global__ __launch_bounds__(256, 2)
void bgemm(const __nv_bfloat16* __restrict__ Ah, const __nv_bfloat16* __restrict__ Al,
           const __nv_bfloat16* __restrict__ Bh, const __nv_bfloat16* __restrict__ Bl,
           float* __restrict__ Cout, int N, int K)
{
    extern __shared__ char smc[];
    const uint32_t sb = smem_u32(smc);

    const int tid  = threadIdx.x;
    const int wid  = tid >> 5;
    const int lane = tid & 31;
    const int g    = lane >> 2;
    const int tig  = lane & 3;
    const int lq   = lane >> 3;
    const int lr   = lane & 7;
    const int warp_m = wid >> 2;
    const int warp_n = wid & 3;
    const int bm = blockIdx.y;
    const int bn = blockIdx.x;

    const char* gsrc[4] = {
        (const char*)(Ah + (size_t)bm * 128 * K),
        (const char*)(Al + (size_t)bm * 128 * K),
        (const char*)(Bh + (size_t)bn * 128 * K),
        (const char*)(Bl + (size_t)bn * 128 * K)
    };
    const size_t grs = (size_t)K * 2;

    float acc[4][4][4];
#pragma unroll
    for (int i = 0; i < 4; i++)
#pragma unroll
        for (int j = 0; j < 4; j++)
#pragma unroll
            for (int e = 0; e < 4; e++) acc[i][j][e] = 0.0f;

    const int NT = K / 32;

#pragma unroll
    for (int p = 0; p < 8; p++) {
        const int c   = tid + p * 256;
        const int mat = c >> 9;
        const int r   = (c >> 2) & 127;
        const int q   = (c & 3) * 16;
        cp_async16(sb + mat * MATB + r * (PB * 2) + q,
                   gsrc[mat] + (size_t)r * grs + q);
    }
    cp_commit();
    cp_wait0();
    __syncthreads();

    const uint32_t aRow = lr + (lq & 1) * 8;
    const uint32_t aCol = (lq >> 1) * 16;
    const uint32_t bRow = lr + (lq >> 1) * 8;
    const uint32_t bCol = (lq & 1) * 16;

    for (int t = 0; t < NT; t++) {
        const int buf = t & 1;

        if (t + 1 < NT) {
            const uint32_t db = sb + (buf ^ 1) * BUFB;
            const size_t kb = (size_t)(t + 1) * 64;
#pragma unroll
            for (int p = 0; p < 8; p++) {
                const int c   = tid + p * 256;
                const int mat = c >> 9;
                const int r   = (c >> 2) & 127;
                const int q   = (c & 3) * 16;
                cp_async16(db + mat * MATB + r * (PB * 2) + q,
                           gsrc[mat] + (size_t)r * grs + kb + q);
            }
            cp_commit();
        }

        const uint32_t base = sb + buf * BUFB;
#pragma unroll
        for (int ks = 0; ks < 2; ks++) {
            const uint32_t ko = ks * 32;

            uint32_t ah[4][4], al[4][4], bh[4][2], bl[4][2];
#pragma unroll
            for (int i = 0; i < 4; i++) {
                const uint32_t ao = (warp_m * 64 + i * 16 + aRow) * (PB * 2) + ko + aCol;
                ldsm4(ah[i], base + ao);
                ldsm4(al[i], base + MATB + ao);
            }
#pragma unroll
            for (int jp = 0; jp < 2; jp++) {
                const uint32_t bo = (warp_n * 32 + jp * 16 + bRow) * (PB * 2) + ko + bCol;
                uint32_t th[4], tl[4];
                ldsm4(th, base + 2 * MATB + bo);
                bh[2*jp][0] = th[0]; bh[2*jp][1] = th[1];
                bh[2*jp+1][0] = th[2]; bh[2*jp+1][1] = th[3];
                ldsm4(tl, base + 3 * MATB + bo);
                bl[2*jp][0] = tl[0]; bl[2*jp][1] = tl[1];
                bl[2*jp+1][0] = tl[2]; bl[2*jp+1][1] = tl[3];
            }

#pragma unroll
            for (int i = 0; i < 4; i++)
#pragma unroll
                for (int j = 0; j < 4; j++)
                    mma_bf16(acc[i][j], ah[i], bh[j]);
#pragma unroll
            for (int i = 0; i < 4; i++)
#pragma unroll
                for (int j = 0; j < 4; j++)
                    mma_bf16(acc[i][j], al[i], bh[j]);
#pragma unroll
            for (int i = 0; i < 4; i++)
#pragma unroll
                for (int j = 0; j < 4; j++)
                    mma_bf16(acc[i][j], ah[i], bl[j]);
        }

        if (t + 1 < NT) cp_wait0();
        __syncthreads();
    }

    if (MODE == 1) {
        // plain fp32 store
#pragma unroll
        for (int i = 0; i < 4; i++) {
            const int r0 = bm * 128 + warp_m * 64 + i * 16 + g;
#pragma unroll
            for (int j = 0; j < 4; j++) {
                const int c0 = bn * 128 + warp_n * 32 + j * 8 + tig * 2;
#pragma unroll
                for (int half = 0; half < 2; half++) {
                    const int r = r0 + half * 8;
                    *(float2*)(Cout + (size_t)r * N + c0) =
                        make_float2(acc[i][j][half * 2], acc[i][j][half * 2 + 1]);
                }
            }
        }
        return;
    }

    // ---- MODE 0 fused epilogue: stage fp32 tile into (now free) smem ----
    __syncthreads();   // all warps done reading operand smem
    float* Cs = (float*)smc;
#pragma unroll
    for (int i = 0; i < 4; i++) {
        const int rl0 = warp_m * 64 + i * 16 + g;
#pragma unroll
        for (int j = 0; j < 4; j++) {
            const int cl = warp_n * 32 + j * 8 + tig * 2;
#pragma unroll
            for (int half = 0; half < 2; half++) {
                const int rl = rl0 + half * 8;
                *(float2*)&Cs[rl * CPIT + cl] =
                    make_float2(acc[i][j][half * 2], acc[i][j][half * 2 + 1]);
            }
        }
    }
    __syncthreads();

    const int part  = bn >> 3;                 // 0:q 1:k 2:v
    const int b     = (bm * 128) >> 11;        // batch
    const int trow0 = (bm * 128) & (T_ - 1);   // first t of tile
    const int h0    = (bn & 7) * 2;            // first head covered

    if (part < 2) {
        __nv_bfloat16* dh = (part == 0) ? g_qh : g_kh;
        __nv_bfloat16* dl = (part == 0) ? g_ql : g_kl;
        // 128 rows x 2 heads x 16 even-j = 4096 items; angles from table
        for (int it = tid; it < 4096; it += 256) {
            const int r  = it >> 5;
            const int hh = (it >> 4) & 1;
            const int j  = (it & 15) * 2;      // even d in [0,32)
            const int t  = trow0 + r;
            const float* row = &Cs[r * CPIT + hh * 64];
            const float a0 = row[j],      a1 = row[j + 1];
            const float b0 = row[j + 32], b1 = row[j + 33];
            const float2 sc_s = *(const float2*)&g_rsin[t * 32 + j];
            const float2 sc_c = *(const float2*)&g_rcos[t * 32 + j];
            const float s0 = sc_s.x, s1 = sc_s.y;
            const float c0 = sc_c.x, c1 = sc_c.y;
            const float o0 = a0 * c0 - b0 * s0, o1 = a1 * c1 - b1 * s1;  // d, d+1
            const float p0 = b0 * c0 + a0 * s0, p1 = b1 * c1 + a1 * s1;  // d+32, d+33
            const size_t basep = ((size_t)(b * H_ + h0 + hh) * T_ + t) * HD_;
            uint32_t ph, pl;
            split2(o0, o1, ph, pl);
            *(uint32_t*)(dh + basep + j) = ph;      *(uint32_t*)(dl + basep + j) = pl;
            split2(p0, p1, ph, pl);
            *(uint32_t*)(dh + basep + j + 32) = ph; *(uint32_t*)(dl + basep + j + 32) = pl;
        }
    } else {
        // v: transpose + split -> g_vth/l [bh][d][t]; 128 idx x 64 t-pairs
        for (int it = tid; it < 8192; it += 256) {
            const int d  = it >> 6;            // 0..127 (2 heads x 64)
            const int tp = it & 63;            // t-pair
            const float v0 = Cs[(2 * tp)     * CPIT + d];
            const float v1 = Cs[(2 * tp + 1) * CPIT + d];
            const int hh = d >> 6, dd = d & 63;
            const size_t o = ((size_t)(b * H_ + h0 + hh) * HD_ + dd) * T_ + trow0 + 2 * tp;
            uint32_t ph, pl;
            split2(v0, v1, ph, pl);
            *(uint32_t*)(g_vth + o) = ph;
            *(uint32_t*)(g_vtl + o) = pl;
        }
    }
}

// ---------------------------------------------------------------------------
// Tensor-core flash attention — EXACT R10 structure (single buffer, 2 CTA/SM).
// ---------------------------------------------------------------------------
#define KPIT 72
#define VPIT 136
#define SM_KH 0
#define SM_KL (128 * KPIT)
#define SM_VH (2 * 128 * KPIT)
#define SM_VL (2 * 128 * KPIT + 64 * VPIT)
#define FLASH_SMEM ((2 * 128 * KPIT + 2 * 64 * VPIT) * 2)

__global__ __launch_bounds__(256, 1)
void flash_tc()
{
    extern __shared__ __nv_bfloat16 smb[];
    __nv_bfloat16* Karr[2] = { smb + SM_KH, smb + SM_KL };
    __nv_bfloat16* Varr[2] = { smb + SM_VH, smb + SM_VL };
    const uint32_t skh = smem_u32(smb + SM_KH);
    const uint32_t skl = smem_u32(smb + SM_KL);
    const uint32_t svh = smem_u32(smb + SM_VH);
    const uint32_t svl = smem_u32(smb + SM_VL);

    const int tid  = threadIdx.x;
    const int wid  = tid >> 5;
    const int lane = tid & 31;
    const int g    = lane >> 2;
    const int tig  = lane & 3;
    const int lq   = lane >> 3;
    const int lr   = lane & 7;
    const int qtile = (int)gridDim.x - 1 - (int)blockIdx.x;
    const int bh    = blockIdx.y;

    const size_t qkbase = ((size_t)bh * T_ + (size_t)qtile * 128) * HD_;
    const size_t kvrow0 = (size_t)bh * T_ * HD_;
    const size_t vtbase = (size_t)bh * HD_ * T_;

    const uint32_t aRow = lr + (lq & 1) * 8;
    const uint32_t aCol = (lq >> 1) * 16;
    const uint32_t bRow = lr + (lq >> 1) * 8;
    const uint32_t bCol = (lq & 1) * 16;

    // ---- stage Q, extract A-fragments via ldmatrix, release smem ----
    {
        const __nv_bfloat16* qsrc[2] = { g_qh + qkbase, g_ql + qkbase };
#pragma unroll
        for (int p = 0; p < 8; p++) {
            const int c   = tid + p * 256;
            const int mat = c >> 10;
            const int rem = c & 1023;
            const int r   = rem >> 3;
            const int c8  = (rem & 7) * 8;
            *(uint4*)(Karr[mat] + r * KPIT + c8) =
                *(const uint4*)(qsrc[mat] + r * HD_ + c8);
        }
    }
    __syncthreads();

    uint32_t qfh[4][4], qfl[4][4];
#pragma unroll
    for (int kb = 0; kb < 4; kb++) {
        const uint32_t qo = (16 * wid + aRow) * (KPIT * 2) + kb * 32 + aCol;
        ldsm4(qfh[kb], skh + qo);
        ldsm4(qfl[kb], skl + qo);
    }

    float o[8][4];
#pragma unroll
    for (int nt = 0; nt < 8; nt++)
#pragma unroll
        for (int e = 0; e < 4; e++) o[nt][e] = 0.0f;
    float m0 = -INFINITY, m1 = -INFINITY, l0 = 0.0f, l1 = 0.0f;

    for (int kv = 0; kv <= qtile; kv++) {
        __syncthreads();
        {
            const __nv_bfloat16* ksrc[2] = { g_kh + kvrow0 + (size_t)kv * 128 * HD_,
                                             g_kl + kvrow0 + (size_t)kv * 128 * HD_ };
            const __nv_bfloat16* vsrc[2] = { g_vth + vtbase + (size_t)kv * 128,
                                             g_vtl + vtbase + (size_t)kv * 128 };
#pragma unroll
            for (int p = 0; p < 8; p++) {
                const int c   = tid + p * 256;
                const int mat = c >> 10;
                const int rem = c & 1023;
                const int r   = rem >> 3;
                const int c8  = (rem & 7) * 8;
                *(uint4*)(Karr[mat] + r * KPIT + c8) =
                    *(const uint4*)(ksrc[mat] + r * HD_ + c8);
            }
#pragma unroll
            for (int p = 0; p < 8; p++) {
                const int c   = tid + p * 256;
                const int mat = c >> 10;
                const int rem = c & 1023;
                const int d   = rem >> 4;
                const int c8  = (rem & 15) * 8;
                *(uint4*)(Varr[mat] + d * VPIT + c8) =
                    *(const uint4*)(vsrc[mat] + (size_t)d * T_ + c8);
            }
        }
        __syncthreads();

        // ---- S = Q K^T (split 3-mma) ----
        float cS[16][4];
#pragma unroll
        for (int j = 0; j < 16; j++)
#pragma unroll
            for (int e = 0; e < 4; e++) cS[j][e] = 0.0f;

#pragma unroll
        for (int kb = 0; kb < 4; kb++) {
#pragma unroll
            for (int jp = 0; jp < 8; jp++) {
                const uint32_t koff = (jp * 16 + bRow) * (KPIT * 2) + kb * 32 + bCol;
                uint32_t th[4], tl[4];
                ldsm4(th, skh + koff);
                mma_bf16(cS[2*jp],   qfh[kb], th);
                mma_bf16(cS[2*jp],   qfl[kb], th);
                mma_bf16(cS[2*jp+1], qfh[kb], th + 2);
                mma_bf16(cS[2*jp+1], qfl[kb], th + 2);
                ldsm4(tl, skl + koff);
                mma_bf16(cS[2*jp],   qfh[kb], tl);
                mma_bf16(cS[2*jp+1], qfh[kb], tl + 2);
            }
        }

        // ---- scale + causal mask ----
        const bool diag = (kv == qtile);
        const int row0 = 16 * wid + g;
#pragma unroll
        for (int j = 0; j < 16; j++) {
            const int col0 = j * 8 + 2 * tig;
            cS[j][0] *= 0.125f; cS[j][1] *= 0.125f;
            cS[j][2] *= 0.125f; cS[j][3] *= 0.125f;
            if (diag) {
                if (col0     > row0)     cS[j][0] = -1e30f;
                if (col0 + 1 > row0)     cS[j][1] = -1e30f;
                if (col0     > row0 + 8) cS[j][2] = -1e30f;
                if (col0 + 1 > row0 + 8) cS[j][3] = -1e30f;
            }
        }

        // ---- online softmax ----
        float mx0 = -INFINITY, mx1 = -INFINITY;
#pragma unroll
        for (int j = 0; j < 16; j++) {
            mx0 = fmaxf(mx0, fmaxf(cS[j][0], cS[j][1]));
            mx1 = fmaxf(mx1, fmaxf(cS[j][2], cS[j][3]));
        }
        mx0 = fmaxf(mx0, __shfl_xor_sync(0xffffffffu, mx0, 1));
        mx0 = fmaxf(mx0, __shfl_xor_sync(0xffffffffu, mx0, 2));
        mx1 = fmaxf(mx1, __shfl_xor_sync(0xffffffffu, mx1, 1));
        mx1 = fmaxf(mx1, __shfl_xor_sync(0xffffffffu, mx1, 2));

        const float nm0 = fmaxf(m0, mx0), nm1 = fmaxf(m1, mx1);
        const float al0 = __expf(m0 - nm0), al1 = __expf(m1 - nm1);
        m0 = nm0; m1 = nm1;

        float rs0 = 0.0f, rs1 = 0.0f;
#pragma unroll
        for (int j = 0; j < 16; j++) {
            cS[j][0] = __expf(cS[j][0] - m0);
            cS[j][1] = __expf(cS[j][1] - m0);
            cS[j][2] = __expf(cS[j][2] - m1);
            cS[j][3] = __expf(cS[j][3] - m1);
            rs0 += cS[j][0] + cS[j][1];
            rs1 += cS[j][2] + cS[j][3];
        }
        rs0 += __shfl_xor_sync(0xffffffffu, rs0, 1);
        rs0 += __shfl_xor_sync(0xffffffffu, rs0, 2);
        rs1 += __shfl_xor_sync(0xffffffffu, rs1, 1);
        rs1 += __shfl_xor_sync(0xffffffffu, rs1, 2);
        l0 = l0 * al0 + rs0;
        l1 = l1 * al1 + rs1;

#pragma unroll
        for (int nt = 0; nt < 8; nt++) {
            o[nt][0] *= al0; o[nt][1] *= al0;
            o[nt][2] *= al1; o[nt][3] *= al1;
        }

        // ---- PV ----
#pragma unroll
        for (int kb2 = 0; kb2 < 8; kb2++) {
            uint32_t aph[4], apl[4];
            split2(cS[2*kb2][0],   cS[2*kb2][1],   aph[0], apl[0]);
            split2(cS[2*kb2][2],   cS[2*kb2][3],   aph[1], apl[1]);
            split2(cS[2*kb2+1][0], cS[2*kb2+1][1], aph[2], apl[2]);
            split2(cS[2*kb2+1][2], cS[2*kb2+1][3], aph[3], apl[3]);
#pragma unroll
            for (int np = 0; np < 4; np++) {
                const uint32_t voff = (np * 16 + bRow) * (VPIT * 2) + kb2 * 32 + bCol;
                uint32_t th[4], tl[4];
                ldsm4(th, svh + voff);
                mma_bf16(o[2*np],   aph, th);
                mma_bf16(o[2*np],   apl, th);
                mma_bf16(o[2*np+1], aph, th + 2);
                mma_bf16(o[2*np+1], apl, th + 2);
                ldsm4(tl, svl + voff);
                mma_bf16(o[2*np],   aph, tl);
                mma_bf16(o[2*np+1], aph, tl + 2);
            }
        }
    }

    // ---- epilogue ----
    const int b = bh >> 4;
    const int h = bh & 15;
    const int t0 = qtile * 128 + 16 * wid + g;
    const float inv0 = 1.0f / l0, inv1 = 1.0f / l1;
#pragma unroll
    for (int nt = 0; nt < 8; nt++) {
        const int d = nt * 8 + 2 * tig;
        uint32_t ph, pl;
        split2(o[nt][0] * inv0, o[nt][1] * inv0, ph, pl);
        const size_t off0 = ((size_t)b * T_ + t0) * D_ + h * HD_ + d;
        *(uint32_t*)(g_atth + off0) = ph;
        *(uint32_t*)(g_attl + off0) = pl;
        split2(o[nt][2] * inv1, o[nt][3] * inv1, ph, pl);
        const size_t off1 = ((size_t)b * T_ + t0 + 8) * D_ + h * HD_ + d;
        *(uint32_t*)(g_atth + off1) = ph;
        *(uint32_t*)(g_attl + off1) = pl;
    }
}

// ---------------------------------------------------------------------------
extern "C" void kernel_launch(void* const* d_in, const int* in_sizes, int n_in,
                              void* d_out, int out_size)
{
    const float* x     = (const float*)d_in[0];
    // d_in[1] = mask (causal, static — ignored)
    const float* w_qkv = (const float*)d_in[2];
    const float* w_out = (const float*)d_in[3];
    float* out = (float*)d_out;

    cudaFuncSetAttribute(bgemm<0>, cudaFuncAttributeMaxDynamicSharedMemorySize, BGEMM_SMEM);
    cudaFuncSetAttribute(bgemm<1>, cudaFuncAttributeMaxDynamicSharedMemorySize, BGEMM_SMEM);
    cudaFuncSetAttribute(flash_tc, cudaFuncAttributeMaxDynamicSharedMemorySize, FLASH_SMEM);

    __nv_bfloat16 *xh, *xl, *wqh, *wql, *woh, *wol, *ath, *atl;
    cudaGetSymbolAddress((void**)&xh,  g_xh);     cudaGetSymbolAddress((void**)&xl,  g_xl);
    cudaGetSymbolAddress((void**)&wqh, g_wqkvTh); cudaGetSymbolAddress((void**)&wql, g_wqkvTl);
    cudaGetSymbolAddress((void**)&woh, g_woutTh); cudaGetSymbolAddress((void**)&wol, g_woutTl);
    cudaGetSymbolAddress((void**)&ath, g_atth);   cudaGetSymbolAddress((void**)&atl, g_attl);

    // 0) RoPE table; split x; split+transpose weights
    rope_table_kernel<<<(T_ * 32) / 256, 256>>>();
    split4_kernel<<<(M_*D_/4 + 255)/256, 256>>>((const float4*)x,
        (__nv_bfloat162*)xh, (__nv_bfloat162*)xl, M_*D_/4);
    splitT_kernel<<<dim3(NQKV_/32, D_/32), dim3(32, 8)>>>(w_qkv, wqh, wql, D_, NQKV_);
    splitT_kernel<<<dim3(D_/32,  D_/32), dim3(32, 8)>>>(w_out, woh, wol, D_, D_);

    // 1) qkv = x @ w_qkv (tensor) with fused table-RoPE/split/transpose epilogue
    bgemm<0><<<dim3(NQKV_/128, M_/128), 256, BGEMM_SMEM>>>(xh, xl, wqh, wql,
                                                           nullptr, NQKV_, K_);

    // 2) tensor-core causal flash attention
    flash_tc<<<dim3(T_ / 128, B_ * H_), 256, FLASH_SMEM>>>();

    // 3) out = att @ w_out (tensor)
    bgemm<1><<<dim3(D_/128, M_/128), 256, BGEMM_SMEM>>>(ath, atl, woh, wol,
                                                        out, D_, K_);
}

// round 17
// speedup vs baseline: 1.0844x; 1.0129x over previous
#include <cuda_runtime.h>
#include <cuda_bf16.h>
#include <math.h>
#include <stdint.h>

// Problem constants
#define B_   2
#define H_   16
#define T_   2048
#define D_   1024
#define HD_  64
#define M_   (B_*T_)      // 4096 rows
#define NQKV_ (3*D_)      // 3072
#define K_   1024

// bf16 split operands (device globals: allocation-free rule)
__device__ __align__(16) __nv_bfloat16 g_xh[M_*D_],    g_xl[M_*D_];
__device__ __align__(16) __nv_bfloat16 g_wqkvTh[NQKV_*D_], g_wqkvTl[NQKV_*D_];
__device__ __align__(16) __nv_bfloat16 g_woutTh[D_*D_],   g_woutTl[D_*D_];
__device__ __align__(16) __nv_bfloat16 g_atth[M_*D_],  g_attl[M_*D_];
__device__ __align__(16) __nv_bfloat16 g_qh[B_*H_*T_*HD_], g_ql[B_*H_*T_*HD_];  // [bh][t][d]
__device__ __align__(16) __nv_bfloat16 g_kh[B_*H_*T_*HD_], g_kl[B_*H_*T_*HD_];  // [bh][t][d]
__device__ __align__(16) __nv_bfloat16 g_vth[B_*H_*T_*HD_], g_vtl[B_*H_*T_*HD_]; // [bh][d][t]
// RoPE sin/cos table: [t][j], j in [0,32)
__device__ __align__(16) float g_rsin[T_*32], g_rcos[T_*32];

__device__ __forceinline__ uint32_t smem_u32(const void* p) {
    uint32_t a;
    asm("{ .reg .u64 t; cvta.to.shared.u64 t, %1; cvt.u32.u64 %0, t; }" : "=r"(a) : "l"(p));
    return a;
}
__device__ __forceinline__ void cp_async16(uint32_t dst, const void* src) {
    asm volatile("cp.async.cg.shared.global [%0], [%1], 16;" :: "r"(dst), "l"(src));
}
__device__ __forceinline__ void cp_commit() { asm volatile("cp.async.commit_group;" ::: "memory"); }
__device__ __forceinline__ void cp_wait0()  { asm volatile("cp.async.wait_group 0;" ::: "memory"); }
__device__ __forceinline__ void ldsm4(uint32_t r[4], uint32_t addr) {
    asm volatile("ldmatrix.sync.aligned.m8n8.x4.shared.b16 {%0,%1,%2,%3}, [%4];"
        : "=r"(r[0]), "=r"(r[1]), "=r"(r[2]), "=r"(r[3]) : "r"(addr));
}
__device__ __forceinline__ void mma_bf16(float c[4], const uint32_t a[4], const uint32_t b[2]) {
    asm volatile(
        "mma.sync.aligned.m16n8k16.row.col.f32.bf16.bf16.f32 "
        "{%0,%1,%2,%3}, {%4,%5,%6,%7}, {%8,%9}, {%0,%1,%2,%3};"
        : "+f"(c[0]), "+f"(c[1]), "+f"(c[2]), "+f"(c[3])
        : "r"(a[0]), "r"(a[1]), "r"(a[2]), "r"(a[3]), "r"(b[0]), "r"(b[1]));
}
__device__ __forceinline__ void split1(float v, __nv_bfloat16& h, __nv_bfloat16& l) {
    h = __float2bfloat16(v);
    l = __float2bfloat16(v - __bfloat162float(h));
}
__device__ __forceinline__ void split2(float x, float y, uint32_t& h, uint32_t& l) {
    __nv_bfloat16 hx, lx, hy, ly;
    split1(x, hx, lx); split1(y, hy, ly);
    __nv_bfloat162 hv(hx, hy), lv(lx, ly);
    h = *(uint32_t*)&hv; l = *(uint32_t*)&lv;
}

// ---------------------------------------------------------------------------
// Unified prep kernel: rope table + x split + both weight transpose-splits.
// Block ranges (256 threads each):
//   [0, NB_TAB)                       rope table
//   [NB_TAB, +NB_X)                   split4(x)
//   [.., +NB_WQ)                      splitT(w_qkv)
//   [.., +NB_WO)                      splitT(w_out)
// ---------------------------------------------------------------------------
#define NB_TAB (T_ * 32 / 256)            // 256
#define NB_X   (M_ * D_ / 4 / 256)        // 4096
#define NB_WQ  ((NQKV_ / 32) * (D_ / 32)) // 3072
#define NB_WO  ((D_ / 32) * (D_ / 32))    // 1024
#define NB_ALL (NB_TAB + NB_X + NB_WQ + NB_WO)

__device__ __forceinline__ void do_splitT(const float* __restrict__ src,
                                          __nv_bfloat16* __restrict__ hT,
                                          __nv_bfloat16* __restrict__ lT,
                                          int R, int C, int blk, int tid)
{
    __shared__ float tile[32][33];
    const int bx = (blk % (C / 32)) * 32;
    const int by = (blk / (C / 32)) * 32;
    const int tx = tid & 31, ty = tid >> 5;   // 32 x 8
#pragma unroll
    for (int i = 0; i < 32; i += 8)
        tile[ty + i][tx] = src[(size_t)(by + ty + i) * C + bx + tx];
    __syncthreads();
#pragma unroll
    for (int i = 0; i < 32; i += 8) {
        const float v = tile[tx][ty + i];
        __nv_bfloat16 h, l;
        split1(v, h, l);
        const size_t o = (size_t)(bx + ty + i) * R + by + tx;
        hT[o] = h; lT[o] = l;
    }
}

__global__ void prep_kernel(const float4* __restrict__ x4,
                            const float* __restrict__ w_qkv,
                            const float* __restrict__ w_out)
{
    const int blk = blockIdx.x;
    const int tid = threadIdx.x;

    if (blk < NB_TAB) {
        // rope table
        const int idx = blk * 256 + tid;
        const int j = idx & 31;
        const int t = idx >> 5;
        const float f = exp2f(-(float)j * (13.287712379549449f / 32.0f));
        float s, c;
        sincosf((float)t * f, &s, &c);
        g_rsin[idx] = s;
        g_rcos[idx] = c;
    } else if (blk < NB_TAB + NB_X) {
        // split x (float4 granularity)
        const int i = (blk - NB_TAB) * 256 + tid;
        const float4 v = x4[i];
        __nv_bfloat16 hx, lx, hy, ly, hz, lz, hw, lw;
        split1(v.x, hx, lx); split1(v.y, hy, ly);
        split1(v.z, hz, lz); split1(v.w, hw, lw);
        ((__nv_bfloat162*)g_xh)[2*i]   = __nv_bfloat162(hx, hy);
        ((__nv_bfloat162*)g_xh)[2*i+1] = __nv_bfloat162(hz, hw);
        ((__nv_bfloat162*)g_xl)[2*i]   = __nv_bfloat162(lx, ly);
        ((__nv_bfloat162*)g_xl)[2*i+1] = __nv_bfloat162(lz, lw);
    } else if (blk < NB_TAB + NB_X + NB_WQ) {
        do_splitT(w_qkv, g_wqkvTh, g_wqkvTl, D_, NQKV_, blk - NB_TAB - NB_X, tid);
    } else {
        do_splitT(w_out, g_woutTh, g_woutTl, D_, D_, blk - NB_TAB - NB_X - NB_WQ, tid);
    }
}

// ---------------------------------------------------------------------------
// bf16 split-GEMM with ldmatrix fragment loading.
// MODE 0: fused epilogue (table-driven RoPE + split; V transpose + split)
// MODE 1: plain fp32 store to Cout.
// ---------------------------------------------------------------------------
#define PB    40
#define MATB  (128 * PB * 2)
#define BUFB  (4 * MATB)
#define BGEMM_SMEM (2 * BUFB)     // 81920 B; epilogue reuses as 128x132 fp32
#define CPIT  132                 // EVEN pitch: float2 stores stay 8B-aligned

template<int MODE>
__global__ __launch_bounds__(256, 2)
void bgemm(const __nv_bfloat16* __restrict__ Ah, const __nv_bfloat16* __restrict__ Al,
           const __nv_bfloat16* __restrict__ Bh, const __nv_bfloat16* __restrict__ Bl,
           float* __restrict__ Cout, int N, int K)
{
    extern __shared__ char smc[];
    const uint32_t sb = smem_u32(smc);

    const int tid  = threadIdx.x;
    const int wid  = tid >> 5;
    const int lane = tid & 31;
    const int g    = lane >> 2;
    const int tig  = lane & 3;
    const int lq   = lane >> 3;
    const int lr   = lane & 7;
    const int warp_m = wid >> 2;
    const int warp_n = wid & 3;
    const int bm = blockIdx.y;
    const int bn = blockIdx.x;

    const char* gsrc[4] = {
        (const char*)(Ah + (size_t)bm * 128 * K),
        (const char*)(Al + (size_t)bm * 128 * K),
        (const char*)(Bh + (size_t)bn * 128 * K),
        (const char*)(Bl + (size_t)bn * 128 * K)
    };
    const size_t grs = (size_t)K * 2;

    float acc[4][4][4];
#pragma unroll
    for (int i = 0; i < 4; i++)
#pragma unroll
        for (int j = 0; j < 4; j++)
#pragma unroll
            for (int e = 0; e < 4; e++) acc[i][j][e] = 0.0f;

    const int NT = K / 32;

#pragma unroll
    for (int p = 0; p < 8; p++) {
        const int c   = tid + p * 256;
        const int mat = c >> 9;
        const int r   = (c >> 2) & 127;
        const int q   = (c & 3) * 16;
        cp_async16(sb + mat * MATB + r * (PB * 2) + q,
                   gsrc[mat] + (size_t)r * grs + q);
    }
    cp_commit();
    cp_wait0();
    __syncthreads();

    const uint32_t aRow = lr + (lq & 1) * 8;
    const uint32_t aCol = (lq >> 1) * 16;
    const uint32_t bRow = lr + (lq >> 1) * 8;
    const uint32_t bCol = (lq & 1) * 16;

    for (int t = 0; t < NT; t++) {
        const int buf = t & 1;

        if (t + 1 < NT) {
            const uint32_t db = sb + (buf ^ 1) * BUFB;
            const size_t kb = (size_t)(t + 1) * 64;
#pragma unroll
            for (int p = 0; p < 8; p++) {
                const int c   = tid + p * 256;
                const int mat = c >> 9;
                const int r   = (c >> 2) & 127;
                const int q   = (c & 3) * 16;
                cp_async16(db + mat * MATB + r * (PB * 2) + q,
                           gsrc[mat] + (size_t)r * grs + kb + q);
            }
            cp_commit();
        }

        const uint32_t base = sb + buf * BUFB;
#pragma unroll
        for (int ks = 0; ks < 2; ks++) {
            const uint32_t ko = ks * 32;

            uint32_t ah[4][4], al[4][4], bh[4][2], bl[4][2];
#pragma unroll
            for (int i = 0; i < 4; i++) {
                const uint32_t ao = (warp_m * 64 + i * 16 + aRow) * (PB * 2) + ko + aCol;
                ldsm4(ah[i], base + ao);
                ldsm4(al[i], base + MATB + ao);
            }
#pragma unroll
            for (int jp = 0; jp < 2; jp++) {
                const uint32_t bo = (warp_n * 32 + jp * 16 + bRow) * (PB * 2) + ko + bCol;
                uint32_t th[4], tl[4];
                ldsm4(th, base + 2 * MATB + bo);
                bh[2*jp][0] = th[0]; bh[2*jp][1] = th[1];
                bh[2*jp+1][0] = th[2]; bh[2*jp+1][1] = th[3];
                ldsm4(tl, base + 3 * MATB + bo);
                bl[2*jp][0] = tl[0]; bl[2*jp][1] = tl[1];
                bl[2*jp+1][0] = tl[2]; bl[2*jp+1][1] = tl[3];
            }

#pragma unroll
            for (int i = 0; i < 4; i++)
#pragma unroll
                for (int j = 0; j < 4; j++)
                    mma_bf16(acc[i][j], ah[i], bh[j]);
#pragma unroll
            for (int i = 0; i < 4; i++)
#pragma unroll
                for (int j = 0; j < 4; j++)
                    mma_bf16(acc[i][j], al[i], bh[j]);
#pragma unroll
            for (int i = 0; i < 4; i++)
#pragma unroll
                for (int j = 0; j < 4; j++)
                    mma_bf16(acc[i][j], ah[i], bl[j]);
        }

        if (t + 1 < NT) cp_wait0();
        __syncthreads();
    }

    if (MODE == 1) {
        // plain fp32 store
#pragma unroll
        for (int i = 0; i < 4; i++) {
            const int r0 = bm * 128 + warp_m * 64 + i * 16 + g;
#pragma unroll
            for (int j = 0; j < 4; j++) {
                const int c0 = bn * 128 + warp_n * 32 + j * 8 + tig * 2;
#pragma unroll
                for (int half = 0; half < 2; half++) {
                    const int r = r0 + half * 8;
                    *(float2*)(Cout + (size_t)r * N + c0) =
                        make_float2(acc[i][j][half * 2], acc[i][j][half * 2 + 1]);
                }
            }
        }
        return;
    }

    // ---- MODE 0 fused epilogue: stage fp32 tile into (now free) smem ----
    __syncthreads();   // all warps done reading operand smem
    float* Cs = (float*)smc;
#pragma unroll
    for (int i = 0; i < 4; i++) {
        const int rl0 = warp_m * 64 + i * 16 + g;
#pragma unroll
        for (int j = 0; j < 4; j++) {
            const int cl = warp_n * 32 + j * 8 + tig * 2;
#pragma unroll
            for (int half = 0; half < 2; half++) {
                const int rl = rl0 + half * 8;
                *(float2*)&Cs[rl * CPIT + cl] =
                    make_float2(acc[i][j][half * 2], acc[i][j][half * 2 + 1]);
            }
        }
    }
    __syncthreads();

    const int part  = bn >> 3;                 // 0:q 1:k 2:v
    const int b     = (bm * 128) >> 11;        // batch
    const int trow0 = (bm * 128) & (T_ - 1);   // first t of tile
    const int h0    = (bn & 7) * 2;            // first head covered

    if (part < 2) {
        __nv_bfloat16* dh = (part == 0) ? g_qh : g_kh;
        __nv_bfloat16* dl = (part == 0) ? g_ql : g_kl;
        // 128 rows x 2 heads x 16 even-j = 4096 items; angles from table
        for (int it = tid; it < 4096; it += 256) {
            const int r  = it >> 5;
            const int hh = (it >> 4) & 1;
            const int j  = (it & 15) * 2;      // even d in [0,32)
            const int t  = trow0 + r;
            const float* row = &Cs[r * CPIT + hh * 64];
            const float a0 = row[j],      a1 = row[j + 1];
            const float b0 = row[j + 32], b1 = row[j + 33];
            const float2 sc_s = *(const float2*)&g_rsin[t * 32 + j];
            const float2 sc_c = *(const float2*)&g_rcos[t * 32 + j];
            const float s0 = sc_s.x, s1 = sc_s.y;
            const float c0 = sc_c.x, c1 = sc_c.y;
            const float o0 = a0 * c0 - b0 * s0, o1 = a1 * c1 - b1 * s1;  // d, d+1
            const float p0 = b0 * c0 + a0 * s0, p1 = b1 * c1 + a1 * s1;  // d+32, d+33
            const size_t basep = ((size_t)(b * H_ + h0 + hh) * T_ + t) * HD_;
            uint32_t ph, pl;
            split2(o0, o1, ph, pl);
            *(uint32_t*)(dh + basep + j) = ph;      *(uint32_t*)(dl + basep + j) = pl;
            split2(p0, p1, ph, pl);
            *(uint32_t*)(dh + basep + j + 32) = ph; *(uint32_t*)(dl + basep + j + 32) = pl;
        }
    } else {
        // v: transpose + split -> g_vth/l [bh][d][t]; 128 idx x 64 t-pairs
        for (int it = tid; it < 8192; it += 256) {
            const int d  = it >> 6;            // 0..127 (2 heads x 64)
            const int tp = it & 63;            // t-pair
            const float v0 = Cs[(2 * tp)     * CPIT + d];
            const float v1 = Cs[(2 * tp + 1) * CPIT + d];
            const int hh = d >> 6, dd = d & 63;
            const size_t o = ((size_t)(b * H_ + h0 + hh) * HD_ + dd) * T_ + trow0 + 2 * tp;
            uint32_t ph, pl;
            split2(v0, v1, ph, pl);
            *(uint32_t*)(g_vth + o) = ph;
            *(uint32_t*)(g_vtl + o) = pl;
        }
    }
}

// ---------------------------------------------------------------------------
// Tensor-core flash attention — EXACT R10 structure (single buffer, 2 CTA/SM).
// ---------------------------------------------------------------------------
#define KPIT 72
#define VPIT 136
#define SM_KH 0
#define SM_KL (128 * KPIT)
#define SM_VH (2 * 128 * KPIT)
#define SM_VL (2 * 128 * KPIT + 64 * VPIT)
#define FLASH_SMEM ((2 * 128 * KPIT + 2 * 64 * VPIT) * 2)

__global__ __launch_bounds__(256, 1)
void flash_tc()
{
    extern __shared__ __nv_bfloat16 smb[];
    __nv_bfloat16* Karr[2] = { smb + SM_KH, smb + SM_KL };
    __nv_bfloat16* Varr[2] = { smb + SM_VH, smb + SM_VL };
    const uint32_t skh = smem_u32(smb + SM_KH);
    const uint32_t skl = smem_u32(smb + SM_KL);
    const uint32_t svh = smem_u32(smb + SM_VH);
    const uint32_t svl = smem_u32(smb + SM_VL);

    const int tid  = threadIdx.x;
    const int wid  = tid >> 5;
    const int lane = tid & 31;
    const int g    = lane >> 2;
    const int tig  = lane & 3;
    const int lq   = lane >> 3;
    const int lr   = lane & 7;
    const int qtile = (int)gridDim.x - 1 - (int)blockIdx.x;
    const int bh    = blockIdx.y;

    const size_t qkbase = ((size_t)bh * T_ + (size_t)qtile * 128) * HD_;
    const size_t kvrow0 = (size_t)bh * T_ * HD_;
    const size_t vtbase = (size_t)bh * HD_ * T_;

    const uint32_t aRow = lr + (lq & 1) * 8;
    const uint32_t aCol = (lq >> 1) * 16;
    const uint32_t bRow = lr + (lq >> 1) * 8;
    const uint32_t bCol = (lq & 1) * 16;

    // ---- stage Q, extract A-fragments via ldmatrix, release smem ----
    {
        const __nv_bfloat16* qsrc[2] = { g_qh + qkbase, g_ql + qkbase };
#pragma unroll
        for (int p = 0; p < 8; p++) {
            const int c   = tid + p * 256;
            const int mat = c >> 10;
            const int rem = c & 1023;
            const int r   = rem >> 3;
            const int c8  = (rem & 7) * 8;
            *(uint4*)(Karr[mat] + r * KPIT + c8) =
                *(const uint4*)(qsrc[mat] + r * HD_ + c8);
        }
    }
    __syncthreads();

    uint32_t qfh[4][4], qfl[4][4];
#pragma unroll
    for (int kb = 0; kb < 4; kb++) {
        const uint32_t qo = (16 * wid + aRow) * (KPIT * 2) + kb * 32 + aCol;
        ldsm4(qfh[kb], skh + qo);
        ldsm4(qfl[kb], skl + qo);
    }

    float o[8][4];
#pragma unroll
    for (int nt = 0; nt < 8; nt++)
#pragma unroll
        for (int e = 0; e < 4; e++) o[nt][e] = 0.0f;
    float m0 = -INFINITY, m1 = -INFINITY, l0 = 0.0f, l1 = 0.0f;

    for (int kv = 0; kv <= qtile; kv++) {
        __syncthreads();
        {
            const __nv_bfloat16* ksrc[2] = { g_kh + kvrow0 + (size_t)kv * 128 * HD_,
                                             g_kl + kvrow0 + (size_t)kv * 128 * HD_ };
            const __nv_bfloat16* vsrc[2] = { g_vth + vtbase + (size_t)kv * 128,
                                             g_vtl + vtbase + (size_t)kv * 128 };
#pragma unroll
            for (int p = 0; p < 8; p++) {
                const int c   = tid + p * 256;
                const int mat = c >> 10;
                const int rem = c & 1023;
                const int r   = rem >> 3;
                const int c8  = (rem & 7) * 8;
                *(uint4*)(Karr[mat] + r * KPIT + c8) =
                    *(const uint4*)(ksrc[mat] + r * HD_ + c8);
            }
#pragma unroll
            for (int p = 0; p < 8; p++) {
                const int c   = tid + p * 256;
                const int mat = c >> 10;
                const int rem = c & 1023;
                const int d   = rem >> 4;
                const int c8  = (rem & 15) * 8;
                *(uint4*)(Varr[mat] + d * VPIT + c8) =
                    *(const uint4*)(vsrc[mat] + (size_t)d * T_ + c8);
            }
        }
        __syncthreads();

        // ---- S = Q K^T (split 3-mma) ----
        float cS[16][4];
#pragma unroll
        for (int j = 0; j < 16; j++)
#pragma unroll
            for (int e = 0; e < 4; e++) cS[j][e] = 0.0f;

#pragma unroll
        for (int kb = 0; kb < 4; kb++) {
#pragma unroll
            for (int jp = 0; jp < 8; jp++) {
                const uint32_t koff = (jp * 16 + bRow) * (KPIT * 2) + kb * 32 + bCol;
                uint32_t th[4], tl[4];
                ldsm4(th, skh + koff);
                mma_bf16(cS[2*jp],   qfh[kb], th);
                mma_bf16(cS[2*jp],   qfl[kb], th);
                mma_bf16(cS[2*jp+1], qfh[kb], th + 2);
                mma_bf16(cS[2*jp+1], qfl[kb], th + 2);
                ldsm4(tl, skl + koff);
                mma_bf16(cS[2*jp],   qfh[kb], tl);
                mma_bf16(cS[2*jp+1], qfh[kb], tl + 2);
            }
        }

        // ---- scale + causal mask ----
        const bool diag = (kv == qtile);
        const int row0 = 16 * wid + g;
#pragma unroll
        for (int j = 0; j < 16; j++) {
            const int col0 = j * 8 + 2 * tig;
            cS[j][0] *= 0.125f; cS[j][1] *= 0.125f;
            cS[j][2] *= 0.125f; cS[j][3] *= 0.125f;
            if (diag) {
                if (col0     > row0)     cS[j][0] = -1e30f;
                if (col0 + 1 > row0)     cS[j][1] = -1e30f;
                if (col0     > row0 + 8) cS[j][2] = -1e30f;
                if (col0 + 1 > row0 + 8) cS[j][3] = -1e30f;
            }
        }

        // ---- online softmax ----
        float mx0 = -INFINITY, mx1 = -INFINITY;
#pragma unroll
        for (int j = 0; j < 16; j++) {
            mx0 = fmaxf(mx0, fmaxf(cS[j][0], cS[j][1]));
            mx1 = fmaxf(mx1, fmaxf(cS[j][2], cS[j][3]));
        }
        mx0 = fmaxf(mx0, __shfl_xor_sync(0xffffffffu, mx0, 1));
        mx0 = fmaxf(mx0, __shfl_xor_sync(0xffffffffu, mx0, 2));
        mx1 = fmaxf(mx1, __shfl_xor_sync(0xffffffffu, mx1, 1));
        mx1 = fmaxf(mx1, __shfl_xor_sync(0xffffffffu, mx1, 2));

        const float nm0 = fmaxf(m0, mx0), nm1 = fmaxf(m1, mx1);
        const float al0 = __expf(m0 - nm0), al1 = __expf(m1 - nm1);
        m0 = nm0; m1 = nm1;

        float rs0 = 0.0f, rs1 = 0.0f;
#pragma unroll
        for (int j = 0; j < 16; j++) {
            cS[j][0] = __expf(cS[j][0] - m0);
            cS[j][1] = __expf(cS[j][1] - m0);
            cS[j][2] = __expf(cS[j][2] - m1);
            cS[j][3] = __expf(cS[j][3] - m1);
            rs0 += cS[j][0] + cS[j][1];
            rs1 += cS[j][2] + cS[j][3];
        }
        rs0 += __shfl_xor_sync(0xffffffffu, rs0, 1);
        rs0 += __shfl_xor_sync(0xffffffffu, rs0, 2);
        rs1 += __shfl_xor_sync(0xffffffffu, rs1, 1);
        rs1 += __shfl_xor_sync(0xffffffffu, rs1, 2);
        l0 = l0 * al0 + rs0;
        l1 = l1 * al1 + rs1;

#pragma unroll
        for (int nt = 0; nt < 8; nt++) {
            o[nt][0] *= al0; o[nt][1] *= al0;
            o[nt][2] *= al1; o[nt][3] *= al1;
        }

        // ---- PV ----
#pragma unroll
        for (int kb2 = 0; kb2 < 8; kb2++) {
            uint32_t aph[4], apl[4];
            split2(cS[2*kb2][0],   cS[2*kb2][1],   aph[0], apl[0]);
            split2(cS[2*kb2][2],   cS[2*kb2][3],   aph[1], apl[1]);
            split2(cS[2*kb2+1][0], cS[2*kb2+1][1], aph[2], apl[2]);
            split2(cS[2*kb2+1][2], cS[2*kb2+1][3], aph[3], apl[3]);
#pragma unroll
            for (int np = 0; np < 4; np++) {
                const uint32_t voff = (np * 16 + bRow) * (VPIT * 2) + kb2 * 32 + bCol;
                uint32_t th[4], tl[4];
                ldsm4(th, svh + voff);
                mma_bf16(o[2*np],   aph, th);
                mma_bf16(o[2*np],   apl, th);
                mma_bf16(o[2*np+1], aph, th + 2);
                mma_bf16(o[2*np+1], apl, th + 2);
                ldsm4(tl, svl + voff);
                mma_bf16(o[2*np],   aph, tl);
                mma_bf16(o[2*np+1], aph, tl + 2);
            }
        }
    }

    // ---- epilogue ----
    const int b = bh >> 4;
    const int h = bh & 15;
    const int t0 = qtile * 128 + 16 * wid + g;
    const float inv0 = 1.0f / l0, inv1 = 1.0f / l1;
#pragma unroll
    for (int nt = 0; nt < 8; nt++) {
        const int d = nt * 8 + 2 * tig;
        uint32_t ph, pl;
        split2(o[nt][0] * inv0, o[nt][1] * inv0, ph, pl);
        const size_t off0 = ((size_t)b * T_ + t0) * D_ + h * HD_ + d;
        *(uint32_t*)(g_atth + off0) = ph;
        *(uint32_t*)(g_attl + off0) = pl;
        split2(o[nt][2] * inv1, o[nt][3] * inv1, ph, pl);
        const size_t off1 = ((size_t)b * T_ + t0 + 8) * D_ + h * HD_ + d;
        *(uint32_t*)(g_atth + off1) = ph;
        *(uint32_t*)(g_attl + off1) = pl;
    }
}

// ---------------------------------------------------------------------------
extern "C" void kernel_launch(void* const* d_in, const int* in_sizes, int n_in,
                              void* d_out, int out_size)
{
    const float* x     = (const float*)d_in[0];
    // d_in[1] = mask (causal, static — ignored)
    const float* w_qkv = (const float*)d_in[2];
    const float* w_out = (const float*)d_in[3];
    float* out = (float*)d_out;

    cudaFuncSetAttribute(bgemm<0>, cudaFuncAttributeMaxDynamicSharedMemorySize, BGEMM_SMEM);
    cudaFuncSetAttribute(bgemm<1>, cudaFuncAttributeMaxDynamicSharedMemorySize, BGEMM_SMEM);
    cudaFuncSetAttribute(flash_tc, cudaFuncAttributeMaxDynamicSharedMemorySize, FLASH_SMEM);

    __nv_bfloat16 *xh, *xl, *wqh, *wql, *woh, *wol, *ath, *atl;
    cudaGetSymbolAddress((void**)&xh,  g_xh);     cudaGetSymbolAddress((void**)&xl,  g_xl);
    cudaGetSymbolAddress((void**)&wqh, g_wqkvTh); cudaGetSymbolAddress((void**)&wql, g_wqkvTl);
    cudaGetSymbolAddress((void**)&woh, g_woutTh); cudaGetSymbolAddress((void**)&wol, g_woutTl);
    cudaGetSymbolAddress((void**)&ath, g_atth);   cudaGetSymbolAddress((void**)&atl, g_attl);

    // 0) all feeders in ONE launch: rope table + x split + weight T-splits
    prep_kernel<<<NB_ALL, 256>>>((const float4*)x, w_qkv, w_out);

    // 1) qkv = x @ w_qkv (tensor) with fused table-RoPE/split/transpose epilogue
    bgemm<0><<<dim3(NQKV_/128, M_/128), 256, BGEMM_SMEM>>>(xh, xl, wqh, wql,
                                                           nullptr, NQKV_, K_);

    // 2) tensor-core causal flash attention
    flash_tc<<<dim3(T_ / 128, B_ * H_), 256, FLASH_SMEM>>>();

    // 3) out = att @ w_out (tensor)
    bgemm<1><<<dim3(D_/128, M_/128), 256, BGEMM_SMEM>>>(ath, atl, woh, wol,
                                                        out, D_, K_);
}